// round 5
// baseline (speedup 1.0000x reference)
#include <cuda_runtime.h>
#include <cuda_bf16.h>
#include <cstdint>

// Problem constants
#define BATCH   2
#define SEQ     2048
#define EMBED   1024
#define NHEADS  16
#define HDIM    64
#define D3      (3 * EMBED)          // 3072
#define MROWS   (BATCH * SEQ)        // 4096

// ---------------------------------------------------------------------------
// Scratch (static device globals: allocation-free per harness rules)
// ---------------------------------------------------------------------------
__device__ float g_qkv [(size_t)MROWS * D3];      // (4096, 3072)

__device__ __align__(16) __nv_bfloat16 g_x_hi [(size_t)MROWS * EMBED];
__device__ __align__(16) __nv_bfloat16 g_x_lo [(size_t)MROWS * EMBED];
__device__ __align__(16) __nv_bfloat16 g_w1_hi[(size_t)D3 * EMBED];
__device__ __align__(16) __nv_bfloat16 g_w1_lo[(size_t)D3 * EMBED];
__device__ __align__(16) __nv_bfloat16 g_w2_hi[(size_t)EMBED * EMBED];
__device__ __align__(16) __nv_bfloat16 g_w2_lo[(size_t)EMBED * EMBED];
__device__ __align__(16) __nv_bfloat16 g_a_hi [(size_t)MROWS * EMBED];
__device__ __align__(16) __nv_bfloat16 g_a_lo [(size_t)MROWS * EMBED];

// ---------------------------------------------------------------------------
// PTX helpers (base sm_103-legal: ldmatrix / mma.sync / cp.async only)
// ---------------------------------------------------------------------------
__device__ __forceinline__ uint32_t smem_u32(const void* p) {
    uint32_t a;
    asm("{ .reg .u64 t; cvta.to.shared.u64 t, %1; cvt.u32.u64 %0, t; }" : "=r"(a) : "l"(p));
    return a;
}
__device__ __forceinline__ void cp_async16(uint32_t dst, const void* src) {
    asm volatile("cp.async.cg.shared.global [%0], [%1], 16;" :: "r"(dst), "l"(src));
}
__device__ __forceinline__ void cp_commit() {
    asm volatile("cp.async.commit_group;" ::: "memory");
}
template <int N>
__device__ __forceinline__ void cp_wait() {
    asm volatile("cp.async.wait_group %0;" :: "n"(N) : "memory");
}
__device__ __forceinline__ void ldsm_x4(uint32_t* r, uint32_t addr) {
    asm volatile("ldmatrix.sync.aligned.m8n8.x4.shared.b16 {%0,%1,%2,%3}, [%4];"
                 : "=r"(r[0]), "=r"(r[1]), "=r"(r[2]), "=r"(r[3]) : "r"(addr));
}
__device__ __forceinline__ void mma_bf16(float* c, const uint32_t* a, const uint32_t* b) {
    asm volatile(
        "mma.sync.aligned.m16n8k16.row.col.f32.bf16.bf16.f32 "
        "{%0,%1,%2,%3}, {%4,%5,%6,%7}, {%8,%9}, {%0,%1,%2,%3};"
        : "+f"(c[0]), "+f"(c[1]), "+f"(c[2]), "+f"(c[3])
        : "r"(a[0]), "r"(a[1]), "r"(a[2]), "r"(a[3]), "r"(b[0]), "r"(b[1]));
}
__device__ __forceinline__ uint32_t f2tf32(float f) {
    uint32_t r;
    asm("cvt.rna.tf32.f32 %0, %1;" : "=r"(r) : "f"(f));
    return r;
}
__device__ __forceinline__ void mma_tf32(float* c, const uint32_t* a, const uint32_t* b) {
    asm volatile(
        "mma.sync.aligned.m16n8k8.row.col.f32.tf32.tf32.f32 "
        "{%0,%1,%2,%3}, {%4,%5,%6,%7}, {%8,%9}, {%0,%1,%2,%3};"
        : "+f"(c[0]), "+f"(c[1]), "+f"(c[2]), "+f"(c[3])
        : "r"(a[0]), "r"(a[1]), "r"(a[2]), "r"(a[3]), "r"(b[0]), "r"(b[1]));
}

// ---------------------------------------------------------------------------
// fp32 -> (hi, lo) bf16 split, float4-vectorized
// ---------------------------------------------------------------------------
__global__ void split4_kernel(const float* __restrict__ src,
                              __nv_bfloat16* __restrict__ hi,
                              __nv_bfloat16* __restrict__ lo, int n4)
{
    int i = blockIdx.x * blockDim.x + threadIdx.x;
    if (i >= n4) return;
    float4 v = reinterpret_cast<const float4*>(src)[i];
    __nv_bfloat16 h0 = __float2bfloat16(v.x);
    __nv_bfloat16 h1 = __float2bfloat16(v.y);
    __nv_bfloat16 h2 = __float2bfloat16(v.z);
    __nv_bfloat16 h3 = __float2bfloat16(v.w);
    __nv_bfloat162* hp = reinterpret_cast<__nv_bfloat162*>(hi);
    __nv_bfloat162* lp = reinterpret_cast<__nv_bfloat162*>(lo);
    hp[2 * i]     = __nv_bfloat162(h0, h1);
    hp[2 * i + 1] = __nv_bfloat162(h2, h3);
    lp[2 * i]     = __nv_bfloat162(__float2bfloat16(v.x - __bfloat162float(h0)),
                                   __float2bfloat16(v.y - __bfloat162float(h1)));
    lp[2 * i + 1] = __nv_bfloat162(__float2bfloat16(v.z - __bfloat162float(h2)),
                                   __float2bfloat16(v.w - __bfloat162float(h3)));
}

// ---------------------------------------------------------------------------
// 3xBF16 split GEMM via mma.sync: C[M,N] = A[M,K] * B[N,K]^T
// BM=BN=128, BK=32, 256 threads, warp tile 64x32, 3-stage cp.async pipeline.
// ---------------------------------------------------------------------------
#define GBK      32
#define ROWB     80
#define TILE_SB  (128 * ROWB)
#define STAGE_SB (4 * TILE_SB)            // 40960
#define GEMM_SMEM (3 * STAGE_SB)          // 122880

__device__ __forceinline__ void load_stage_mma(uint32_t sbase,
                                               const __nv_bfloat16* __restrict__ Ah,
                                               const __nv_bfloat16* __restrict__ Al,
                                               const __nv_bfloat16* __restrict__ Bh,
                                               const __nv_bfloat16* __restrict__ Bl,
                                               int bm, int bn, int K, int k0, int tid)
{
#pragma unroll
    for (int rep = 0; rep < 2; rep++) {
        int s   = tid + rep * 256;
        int row = s >> 2;
        int ch  = s & 3;
        uint32_t soff = (uint32_t)(row * ROWB + ch * 16);
        size_t ga = (size_t)(bm + row) * K + k0 + ch * 8;
        size_t gb = (size_t)(bn + row) * K + k0 + ch * 8;
        cp_async16(sbase + 0 * TILE_SB + soff, Ah + ga);
        cp_async16(sbase + 1 * TILE_SB + soff, Al + ga);
        cp_async16(sbase + 2 * TILE_SB + soff, Bh + gb);
        cp_async16(sbase + 3 * TILE_SB + soff, Bl + gb);
    }
}

__global__ __launch_bounds__(256, 1) void gemm3bf16_mma(
    const __nv_bfloat16* __restrict__ Ah, const __nv_bfloat16* __restrict__ Al,
    const __nv_bfloat16* __restrict__ Bh, const __nv_bfloat16* __restrict__ Bl,
    float* __restrict__ C, int M, int N, int K)
{
    extern __shared__ __align__(16) char dynsmem[];
    const uint32_t sb = smem_u32(dynsmem);

    const int tid  = threadIdx.x;
    const int lane = tid & 31;
    const int wid  = tid >> 5;
    const int wm   = wid >> 2;
    const int wn   = wid & 3;
    const int bm   = blockIdx.y * 128;
    const int bn   = blockIdx.x * 128;

    float acc[4][4][4];
#pragma unroll
    for (int i = 0; i < 4; i++)
#pragma unroll
        for (int j = 0; j < 4; j++)
#pragma unroll
            for (int k = 0; k < 4; k++) acc[i][j][k] = 0.f;

    const int NIT = K / GBK;

    // prologue: stages 0, 1
    load_stage_mma(sb + 0 * STAGE_SB, Ah, Al, Bh, Bl, bm, bn, K, 0, tid);
    cp_commit();
    load_stage_mma(sb + 1 * STAGE_SB, Ah, Al, Bh, Bl, bm, bn, K, GBK, tid);
    cp_commit();

    const uint32_t a_row_in = (uint32_t)(lane & 15);
    const uint32_t a_kb     = (uint32_t)((lane >> 4) * 16);
    const int g  = lane >> 3;
    const int br = lane & 7;
    const uint32_t b_row_in = (uint32_t)(((g >> 1) * 8) + br);
    const uint32_t b_kb     = (uint32_t)((g & 1) * 16);

    int st_cur = 0, st_ld = 2;

    for (int it = 0; it < NIT; it++) {
        if (it + 2 < NIT) {
            load_stage_mma(sb + (uint32_t)st_ld * STAGE_SB,
                           Ah, Al, Bh, Bl, bm, bn, K, (it + 2) * GBK, tid);
            cp_commit();
            cp_wait<2>();
        } else if (it + 1 < NIT) {
            cp_wait<1>();
        } else {
            cp_wait<0>();
        }
        __syncthreads();

        const uint32_t st = sb + (uint32_t)st_cur * STAGE_SB;

#pragma unroll
        for (int ks = 0; ks < 2; ks++) {
            const uint32_t kb = (uint32_t)(ks * 32);

            uint32_t ah[4][4], al[4][4];
#pragma unroll
            for (int mt = 0; mt < 4; mt++) {
                uint32_t addr = st + (uint32_t)((wm * 64 + mt * 16) + a_row_in) * ROWB + kb + a_kb;
                ldsm_x4(ah[mt], addr);
                ldsm_x4(al[mt], addr + TILE_SB);
            }

            uint32_t bh[4][2], bl[4][2];
#pragma unroll
            for (int bt = 0; bt < 2; bt++) {
                uint32_t addr = st + 2 * TILE_SB +
                                (uint32_t)((wn * 32 + bt * 16) + b_row_in) * ROWB + kb + b_kb;
                uint32_t t4[4];
                ldsm_x4(t4, addr);
                bh[2 * bt][0] = t4[0]; bh[2 * bt][1] = t4[1];
                bh[2 * bt + 1][0] = t4[2]; bh[2 * bt + 1][1] = t4[3];
                ldsm_x4(t4, addr + TILE_SB);
                bl[2 * bt][0] = t4[0]; bl[2 * bt][1] = t4[1];
                bl[2 * bt + 1][0] = t4[2]; bl[2 * bt + 1][1] = t4[3];
            }

#pragma unroll
            for (int mt = 0; mt < 4; mt++)
#pragma unroll
                for (int nt = 0; nt < 4; nt++) {
                    mma_bf16(acc[mt][nt], ah[mt], bh[nt]);
                    mma_bf16(acc[mt][nt], ah[mt], bl[nt]);
                    mma_bf16(acc[mt][nt], al[mt], bh[nt]);
                }
        }
        __syncthreads();

        st_cur = (st_cur + 1) % 3;
        st_ld  = (st_ld + 1) % 3;
    }

#pragma unroll
    for (int mt = 0; mt < 4; mt++) {
        int row = bm + wm * 64 + mt * 16 + (lane >> 2);
#pragma unroll
        for (int nt = 0; nt < 4; nt++) {
            int col = bn + wn * 32 + nt * 8 + (lane & 3) * 2;
            *reinterpret_cast<float2*>(&C[(size_t)row * N + col]) =
                make_float2(acc[mt][nt][0], acc[mt][nt][1]);
            *reinterpret_cast<float2*>(&C[(size_t)(row + 8) * N + col]) =
                make_float2(acc[mt][nt][2], acc[mt][nt][3]);
        }
    }
}

// ---------------------------------------------------------------------------
// TF32 tensor-core causal flash attention.
// CTA = (q-tile of 128, head, batch). 8 warps x 16 q-rows. TK=64 key tiles.
// K/V pre-converted to tf32 in smem once per tile.
// Epilogue writes bf16 hi/lo directly (fused split).
// ---------------------------------------------------------------------------
#define TQA   128
#define TKA   64
#define PADK  68
#define ATT_SMEM ((2 * 64 * PADK + 2 * 128 * PADK) * 4)   // 104448 bytes

__global__ __launch_bounds__(256, 2) void attn_tc_kernel()
{
    extern __shared__ float smf[];
    float* Ksm = smf;
    float* Vsm = smf + 64 * PADK;
    float* Qsm = smf + 2 * 64 * PADK;
    float* Psm = Qsm + 128 * PADK;

    const int tid  = threadIdx.x;
    const int lane = tid & 31;
    const int w    = tid >> 5;
    const int tr   = lane >> 2;      // 0..7
    const int tc   = lane & 3;       // 0..3

    const int qi = (int)gridDim.x - 1 - (int)blockIdx.x;   // big tiles first
    const int h  = blockIdx.y;
    const int b  = blockIdx.z;
    const int qb = qi * TQA;
    const size_t rowbase = (size_t)b * SEQ;

    const float* qptr = g_qkv + rowbase * D3 + h * HDIM;
    const float* kptr = qptr + EMBED;
    const float* vptr = qptr + 2 * EMBED;

    // Stage Q tile (128 x 64) into Qsm, pre-converted to tf32 bit patterns.
    for (int i = tid; i < 128 * 16; i += 256) {
        int r = i >> 4, c4 = (i & 15) * 4;
        float4 v = *reinterpret_cast<const float4*>(qptr + (size_t)(qb + r) * D3 + c4);
        float* dst = Qsm + r * PADK + c4;
        dst[0] = __uint_as_float(f2tf32(v.x));
        dst[1] = __uint_as_float(f2tf32(v.y));
        dst[2] = __uint_as_float(f2tf32(v.z));
        dst[3] = __uint_as_float(f2tf32(v.w));
    }

    const uint32_t ksb = smem_u32(Ksm);
    const uint32_t vsb = smem_u32(Vsm);

    float oacc[8][4];
#pragma unroll
    for (int nt = 0; nt < 8; nt++)
#pragma unroll
        for (int e = 0; e < 4; e++) oacc[nt][e] = 0.f;

    float m0 = -1e30f, m1 = -1e30f, l0 = 0.f, l1 = 0.f;

    const float CSC = 0.18033688f;   // (1/sqrt(64)) * log2(e)
    const int wrow  = qb + w * 16;
    const int gr0   = wrow + tr;
    const int jmax  = (qb + TQA - 1) / TKA;

    for (int j = 0; j <= jmax; j++) {
        const int kb = j * TKA;

        __syncthreads();   // previous tile's smem reads complete
#pragma unroll
        for (int rep = 0; rep < 4; rep++) {
            int i = tid + rep * 256;
            int r = i >> 4, c4 = (i & 15) * 4;
            uint32_t soff = (uint32_t)(r * PADK + c4) * 4;
            cp_async16(ksb + soff, kptr + (size_t)(kb + r) * D3 + c4);
            cp_async16(vsb + soff, vptr + (size_t)(kb + r) * D3 + c4);
        }
        cp_commit();
        cp_wait<0>();
        __syncthreads();

        // Pre-convert K and V tiles to tf32 in place (K|V contiguous in smf)
        for (int i = tid; i < 2 * 64 * PADK; i += 256)
            smf[i] = __uint_as_float(f2tf32(smf[i]));
        __syncthreads();

        if (kb <= wrow + 15) {
            // ---- S = Q @ K^T ----
            float sacc[8][4];
#pragma unroll
            for (int nt = 0; nt < 8; nt++)
#pragma unroll
                for (int e = 0; e < 4; e++) sacc[nt][e] = 0.f;

#pragma unroll
            for (int kt = 0; kt < 8; kt++) {
                uint32_t qa[4];
                const float* qrow = Qsm + (size_t)(w * 16 + tr) * PADK + kt * 8 + tc;
                qa[0] = __float_as_uint(qrow[0]);
                qa[1] = __float_as_uint(qrow[8 * PADK]);
                qa[2] = __float_as_uint(qrow[4]);
                qa[3] = __float_as_uint(qrow[8 * PADK + 4]);
#pragma unroll
                for (int nt = 0; nt < 8; nt++) {
                    uint32_t bb[2];
                    const float* krow = Ksm + (size_t)(nt * 8 + tr) * PADK + kt * 8 + tc;
                    bb[0] = __float_as_uint(krow[0]);
                    bb[1] = __float_as_uint(krow[4]);
                    mma_tf32(sacc[nt], qa, bb);
                }
            }

            // ---- online softmax ----
            const bool need_mask = (kb + TKA - 1) > wrow;
            float mx0 = -1e30f, mx1 = -1e30f;
#pragma unroll
            for (int nt = 0; nt < 8; nt++) {
                int c0 = kb + nt * 8 + 2 * tc;
                float z0 = sacc[nt][0] * CSC;
                float z1 = sacc[nt][1] * CSC;
                float z2 = sacc[nt][2] * CSC;
                float z3 = sacc[nt][3] * CSC;
                if (need_mask) {
                    if (c0     > gr0) z0 = -1e30f;
                    if (c0 + 1 > gr0) z1 = -1e30f;
                    if (c0     > gr0 + 8) z2 = -1e30f;
                    if (c0 + 1 > gr0 + 8) z3 = -1e30f;
                }
                sacc[nt][0] = z0; sacc[nt][1] = z1;
                sacc[nt][2] = z2; sacc[nt][3] = z3;
                mx0 = fmaxf(mx0, fmaxf(z0, z1));
                mx1 = fmaxf(mx1, fmaxf(z2, z3));
            }
            mx0 = fmaxf(mx0, __shfl_xor_sync(0xffffffffu, mx0, 1));
            mx0 = fmaxf(mx0, __shfl_xor_sync(0xffffffffu, mx0, 2));
            mx1 = fmaxf(mx1, __shfl_xor_sync(0xffffffffu, mx1, 1));
            mx1 = fmaxf(mx1, __shfl_xor_sync(0xffffffffu, mx1, 2));

            float m0n = fmaxf(m0, mx0);
            float m1n = fmaxf(m1, mx1);
            float f0 = exp2f(m0 - m0n);
            float f1 = exp2f(m1 - m1n);

            float sum0 = 0.f, sum1 = 0.f;
            float* prow0 = Psm + (size_t)(w * 16 + tr) * PADK + 2 * tc;
            float* prow1 = prow0 + 8 * PADK;
#pragma unroll
            for (int nt = 0; nt < 8; nt++) {
                float p00 = exp2f(sacc[nt][0] - m0n);
                float p01 = exp2f(sacc[nt][1] - m0n);
                float p10 = exp2f(sacc[nt][2] - m1n);
                float p11 = exp2f(sacc[nt][3] - m1n);
                sum0 += p00 + p01;
                sum1 += p10 + p11;
                *reinterpret_cast<float2*>(prow0 + nt * 8) =
                    make_float2(__uint_as_float(f2tf32(p00)), __uint_as_float(f2tf32(p01)));
                *reinterpret_cast<float2*>(prow1 + nt * 8) =
                    make_float2(__uint_as_float(f2tf32(p10)), __uint_as_float(f2tf32(p11)));
            }
            sum0 += __shfl_xor_sync(0xffffffffu, sum0, 1);
            sum0 += __shfl_xor_sync(0xffffffffu, sum0, 2);
            sum1 += __shfl_xor_sync(0xffffffffu, sum1, 1);
            sum1 += __shfl_xor_sync(0xffffffffu, sum1, 2);

            l0 = l0 * f0 + sum0;
            l1 = l1 * f1 + sum1;
            m0 = m0n; m1 = m1n;
#pragma unroll
            for (int nt = 0; nt < 8; nt++) {
                oacc[nt][0] *= f0; oacc[nt][1] *= f0;
                oacc[nt][2] *= f1; oacc[nt][3] *= f1;
            }

            __syncwarp();

            // ---- O += P @ V ----
#pragma unroll
            for (int kt = 0; kt < 8; kt++) {
                uint32_t pa[4];
                const float* prow = Psm + (size_t)(w * 16 + tr) * PADK + kt * 8 + tc;
                pa[0] = __float_as_uint(prow[0]);
                pa[1] = __float_as_uint(prow[8 * PADK]);
                pa[2] = __float_as_uint(prow[4]);
                pa[3] = __float_as_uint(prow[8 * PADK + 4]);
#pragma unroll
                for (int nt = 0; nt < 8; nt++) {
                    uint32_t vb[2];
                    const float* vrow = Vsm + (size_t)(kt * 8 + tc) * PADK + nt * 8 + tr;
                    vb[0] = __float_as_uint(vrow[0]);
                    vb[1] = __float_as_uint(vrow[4 * PADK]);
                    mma_tf32(oacc[nt], pa, vb);
                }
            }
        }
    }

    // Epilogue: normalize, split to bf16 hi/lo, write (fused split)
    float il0 = 1.0f / l0;
    float il1 = 1.0f / l1;
    size_t base0 = (size_t)(rowbase + gr0) * EMBED + h * HDIM + 2 * tc;
    size_t base1 = base0 + 8 * EMBED;
#pragma unroll
    for (int nt = 0; nt < 8; nt++) {
        float o00 = oacc[nt][0] * il0, o01 = oacc[nt][1] * il0;
        float o10 = oacc[nt][2] * il1, o11 = oacc[nt][3] * il1;
        __nv_bfloat16 h00 = __float2bfloat16(o00), h01 = __float2bfloat16(o01);
        __nv_bfloat16 h10 = __float2bfloat16(o10), h11 = __float2bfloat16(o11);
        *reinterpret_cast<__nv_bfloat162*>(&g_a_hi[base0 + nt * 8]) = __nv_bfloat162(h00, h01);
        *reinterpret_cast<__nv_bfloat162*>(&g_a_hi[base1 + nt * 8]) = __nv_bfloat162(h10, h11);
        *reinterpret_cast<__nv_bfloat162*>(&g_a_lo[base0 + nt * 8]) =
            __nv_bfloat162(__float2bfloat16(o00 - __bfloat162float(h00)),
                           __float2bfloat16(o01 - __bfloat162float(h01)));
        *reinterpret_cast<__nv_bfloat162*>(&g_a_lo[base1 + nt * 8]) =
            __nv_bfloat162(__float2bfloat16(o10 - __bfloat162float(h10)),
                           __float2bfloat16(o11 - __bfloat162float(h11)));
    }
}

// ---------------------------------------------------------------------------
// Launch
// ---------------------------------------------------------------------------
extern "C" void kernel_launch(void* const* d_in, const int* in_sizes, int n_in,
                              void* d_out, int out_size)
{
    const float* x     = (const float*)d_in[0];
    const float* qkv_w = (const float*)d_in[1];
    const float* out_w = (const float*)d_in[2];
    float* out = (float*)d_out;

    static bool attr_done = false;
    if (!attr_done) {
        cudaFuncSetAttribute(gemm3bf16_mma, cudaFuncAttributeMaxDynamicSharedMemorySize, GEMM_SMEM);
        cudaFuncSetAttribute(attn_tc_kernel, cudaFuncAttributeMaxDynamicSharedMemorySize, ATT_SMEM);
        attr_done = true;
    }

    __nv_bfloat16 *xh, *xl, *w1h, *w1l, *w2h, *w2l, *ah, *al;
    float *qkv;
    cudaGetSymbolAddress((void**)&xh,  g_x_hi);
    cudaGetSymbolAddress((void**)&xl,  g_x_lo);
    cudaGetSymbolAddress((void**)&w1h, g_w1_hi);
    cudaGetSymbolAddress((void**)&w1l, g_w1_lo);
    cudaGetSymbolAddress((void**)&w2h, g_w2_hi);
    cudaGetSymbolAddress((void**)&w2l, g_w2_lo);
    cudaGetSymbolAddress((void**)&ah,  g_a_hi);
    cudaGetSymbolAddress((void**)&al,  g_a_lo);
    cudaGetSymbolAddress((void**)&qkv, g_qkv);

    // 0) split inputs into bf16 hi/lo (float4 vectorized)
    {
        int n1 = MROWS * EMBED / 4;
        split4_kernel<<<(n1 + 255) / 256, 256>>>(x, xh, xl, n1);
        int n2 = D3 * EMBED / 4;
        split4_kernel<<<(n2 + 255) / 256, 256>>>(qkv_w, w1h, w1l, n2);
        int n3 = EMBED * EMBED / 4;
        split4_kernel<<<(n3 + 255) / 256, 256>>>(out_w, w2h, w2l, n3);
    }

    // 1) QKV projection
    {
        dim3 grid(D3 / 128, MROWS / 128);
        gemm3bf16_mma<<<grid, 256, GEMM_SMEM>>>(xh, xl, w1h, w1l, qkv, MROWS, D3, EMBED);
    }

    // 2) Causal flash attention (tf32 tensor cores, fused bf16 split epilogue)
    {
        dim3 grid(SEQ / TQA, NHEADS, BATCH);
        attn_tc_kernel<<<grid, 256, ATT_SMEM>>>();
    }

    // 3) out projection (reads fused-split attention output)
    {
        dim3 grid(EMBED / 128, MROWS / 128);
        gemm3bf16_mma<<<grid, 256, GEMM_SMEM>>>(ah, al, w2h, w2l, out, MROWS, EMBED, EMBED);
    }
}

// round 6
// speedup vs baseline: 1.1315x; 1.1315x over previous
#include <cuda_runtime.h>
#include <cuda_bf16.h>
#include <cstdint>

// Problem constants
#define BATCH   2
#define SEQ     2048
#define EMBED   1024
#define NHEADS  16
#define HDIM    64
#define D3      (3 * EMBED)          // 3072
#define MROWS   (BATCH * SEQ)        // 4096

// ---------------------------------------------------------------------------
// Scratch (static device globals: allocation-free per harness rules)
// ---------------------------------------------------------------------------
__device__ float g_qkv [(size_t)MROWS * D3];      // (4096, 3072)

__device__ __align__(16) __nv_bfloat16 g_x_hi [(size_t)MROWS * EMBED];
__device__ __align__(16) __nv_bfloat16 g_x_lo [(size_t)MROWS * EMBED];
__device__ __align__(16) __nv_bfloat16 g_w1_hi[(size_t)D3 * EMBED];
__device__ __align__(16) __nv_bfloat16 g_w1_lo[(size_t)D3 * EMBED];
__device__ __align__(16) __nv_bfloat16 g_w2_hi[(size_t)EMBED * EMBED];
__device__ __align__(16) __nv_bfloat16 g_w2_lo[(size_t)EMBED * EMBED];
__device__ __align__(16) __nv_bfloat16 g_a_hi [(size_t)MROWS * EMBED];
__device__ __align__(16) __nv_bfloat16 g_a_lo [(size_t)MROWS * EMBED];

// ---------------------------------------------------------------------------
// PTX helpers (base sm_103-legal: ldmatrix / mma.sync / cp.async only)
// ---------------------------------------------------------------------------
__device__ __forceinline__ uint32_t smem_u32(const void* p) {
    uint32_t a;
    asm("{ .reg .u64 t; cvta.to.shared.u64 t, %1; cvt.u32.u64 %0, t; }" : "=r"(a) : "l"(p));
    return a;
}
__device__ __forceinline__ void cp_async16(uint32_t dst, const void* src) {
    asm volatile("cp.async.cg.shared.global [%0], [%1], 16;" :: "r"(dst), "l"(src));
}
__device__ __forceinline__ void cp_commit() {
    asm volatile("cp.async.commit_group;" ::: "memory");
}
template <int N>
__device__ __forceinline__ void cp_wait() {
    asm volatile("cp.async.wait_group %0;" :: "n"(N) : "memory");
}
__device__ __forceinline__ void ldsm_x4(uint32_t* r, uint32_t addr) {
    asm volatile("ldmatrix.sync.aligned.m8n8.x4.shared.b16 {%0,%1,%2,%3}, [%4];"
                 : "=r"(r[0]), "=r"(r[1]), "=r"(r[2]), "=r"(r[3]) : "r"(addr));
}
__device__ __forceinline__ void mma_bf16(float* c, const uint32_t* a, const uint32_t* b) {
    asm volatile(
        "mma.sync.aligned.m16n8k16.row.col.f32.bf16.bf16.f32 "
        "{%0,%1,%2,%3}, {%4,%5,%6,%7}, {%8,%9}, {%0,%1,%2,%3};"
        : "+f"(c[0]), "+f"(c[1]), "+f"(c[2]), "+f"(c[3])
        : "r"(a[0]), "r"(a[1]), "r"(a[2]), "r"(a[3]), "r"(b[0]), "r"(b[1]));
}
__device__ __forceinline__ uint32_t f2tf32(float f) {
    uint32_t r;
    asm("cvt.rna.tf32.f32 %0, %1;" : "=r"(r) : "f"(f));
    return r;
}
__device__ __forceinline__ void mma_tf32(float* c, const uint32_t* a, const uint32_t* b) {
    asm volatile(
        "mma.sync.aligned.m16n8k8.row.col.f32.tf32.tf32.f32 "
        "{%0,%1,%2,%3}, {%4,%5,%6,%7}, {%8,%9}, {%0,%1,%2,%3};"
        : "+f"(c[0]), "+f"(c[1]), "+f"(c[2]), "+f"(c[3])
        : "r"(a[0]), "r"(a[1]), "r"(a[2]), "r"(a[3]), "r"(b[0]), "r"(b[1]));
}

// ---------------------------------------------------------------------------
// fp32 -> (hi, lo) bf16 split, float4-vectorized
// ---------------------------------------------------------------------------
__global__ void split4_kernel(const float* __restrict__ src,
                              __nv_bfloat16* __restrict__ hi,
                              __nv_bfloat16* __restrict__ lo, int n4)
{
    int i = blockIdx.x * blockDim.x + threadIdx.x;
    if (i >= n4) return;
    float4 v = reinterpret_cast<const float4*>(src)[i];
    __nv_bfloat16 h0 = __float2bfloat16(v.x);
    __nv_bfloat16 h1 = __float2bfloat16(v.y);
    __nv_bfloat16 h2 = __float2bfloat16(v.z);
    __nv_bfloat16 h3 = __float2bfloat16(v.w);
    __nv_bfloat162* hp = reinterpret_cast<__nv_bfloat162*>(hi);
    __nv_bfloat162* lp = reinterpret_cast<__nv_bfloat162*>(lo);
    hp[2 * i]     = __nv_bfloat162(h0, h1);
    hp[2 * i + 1] = __nv_bfloat162(h2, h3);
    lp[2 * i]     = __nv_bfloat162(__float2bfloat16(v.x - __bfloat162float(h0)),
                                   __float2bfloat16(v.y - __bfloat162float(h1)));
    lp[2 * i + 1] = __nv_bfloat162(__float2bfloat16(v.z - __bfloat162float(h2)),
                                   __float2bfloat16(v.w - __bfloat162float(h3)));
}

// ---------------------------------------------------------------------------
// 3xBF16 split GEMM via mma.sync: C[M,N] = A[M,K] * B[N,K]^T
// BM=BN=128, BK=32, 128 threads (4 warps), warp tile 64x64,
// 2-stage cp.async pipeline, 2 CTAs/SM.
// ---------------------------------------------------------------------------
#define GBK      32
#define ROWB     80
#define TILE_SB  (128 * ROWB)
#define STAGE_SB (4 * TILE_SB)            // 40960
#define GEMM_SMEM (2 * STAGE_SB)          // 81920

__device__ __forceinline__ void load_stage_mma(uint32_t sbase,
                                               const __nv_bfloat16* __restrict__ Ah,
                                               const __nv_bfloat16* __restrict__ Al,
                                               const __nv_bfloat16* __restrict__ Bh,
                                               const __nv_bfloat16* __restrict__ Bl,
                                               int bm, int bn, int K, int k0, int tid)
{
#pragma unroll
    for (int rep = 0; rep < 16; rep++) {
        const int t = rep >> 2;                 // tile 0=Ah 1=Al 2=Bh 3=Bl (compile-time)
        int e   = tid + (rep & 3) * 128;        // 0..511 chunk within tile
        int row = e >> 2;
        int ch  = e & 3;
        const __nv_bfloat16* g = (t == 0) ? Ah : (t == 1) ? Al : (t == 2) ? Bh : Bl;
        int rbase = (t < 2) ? bm : bn;
        cp_async16(sbase + (uint32_t)t * TILE_SB + (uint32_t)(row * ROWB + ch * 16),
                   g + (size_t)(rbase + row) * K + k0 + ch * 8);
    }
}

__global__ __launch_bounds__(128, 2) void gemm3bf16_mma(
    const __nv_bfloat16* __restrict__ Ah, const __nv_bfloat16* __restrict__ Al,
    const __nv_bfloat16* __restrict__ Bh, const __nv_bfloat16* __restrict__ Bl,
    float* __restrict__ C, int M, int N, int K)
{
    extern __shared__ __align__(16) char dynsmem[];
    const uint32_t sb = smem_u32(dynsmem);

    const int tid  = threadIdx.x;
    const int lane = tid & 31;
    const int wid  = tid >> 5;            // 0..3
    const int wm   = wid >> 1;            // 0..1 (M, 64 rows each)
    const int wn   = wid & 1;             // 0..1 (N, 64 cols each)
    const int bm   = blockIdx.y * 128;
    const int bn   = blockIdx.x * 128;

    float acc[4][8][4];
#pragma unroll
    for (int i = 0; i < 4; i++)
#pragma unroll
        for (int j = 0; j < 8; j++)
#pragma unroll
            for (int k = 0; k < 4; k++) acc[i][j][k] = 0.f;

    const int NIT = K / GBK;

    load_stage_mma(sb, Ah, Al, Bh, Bl, bm, bn, K, 0, tid);
    cp_commit();

    const uint32_t a_row_in = (uint32_t)(lane & 15);
    const uint32_t a_kb     = (uint32_t)((lane >> 4) * 16);
    const int g  = lane >> 3;
    const int br = lane & 7;
    const uint32_t b_row_in = (uint32_t)(((g >> 1) * 8) + br);
    const uint32_t b_kb     = (uint32_t)((g & 1) * 16);

    for (int it = 0; it < NIT; it++) {
        if (it + 1 < NIT) {
            load_stage_mma(sb + (uint32_t)((it + 1) & 1) * STAGE_SB,
                           Ah, Al, Bh, Bl, bm, bn, K, (it + 1) * GBK, tid);
            cp_commit();
            cp_wait<1>();
        } else {
            cp_wait<0>();
        }
        __syncthreads();

        const uint32_t st = sb + (uint32_t)(it & 1) * STAGE_SB;

#pragma unroll
        for (int ks = 0; ks < 2; ks++) {
            const uint32_t kb = (uint32_t)(ks * 32);

            uint32_t ah[4][4], al[4][4];
#pragma unroll
            for (int mt = 0; mt < 4; mt++) {
                uint32_t addr = st + (uint32_t)((wm * 64 + mt * 16) + a_row_in) * ROWB + kb + a_kb;
                ldsm_x4(ah[mt], addr);
                ldsm_x4(al[mt], addr + TILE_SB);
            }

#pragma unroll
            for (int bt = 0; bt < 4; bt++) {
                uint32_t addr = st + 2 * TILE_SB +
                                (uint32_t)((wn * 64 + bt * 16) + b_row_in) * ROWB + kb + b_kb;
                uint32_t th[4], tl[4];
                ldsm_x4(th, addr);
                ldsm_x4(tl, addr + TILE_SB);
#pragma unroll
                for (int mt = 0; mt < 4; mt++) {
                    mma_bf16(acc[mt][2 * bt],     ah[mt], th);
                    mma_bf16(acc[mt][2 * bt],     ah[mt], tl);
                    mma_bf16(acc[mt][2 * bt],     al[mt], th);
                    mma_bf16(acc[mt][2 * bt + 1], ah[mt], th + 2);
                    mma_bf16(acc[mt][2 * bt + 1], ah[mt], tl + 2);
                    mma_bf16(acc[mt][2 * bt + 1], al[mt], th + 2);
                }
            }
        }
        __syncthreads();
    }

#pragma unroll
    for (int mt = 0; mt < 4; mt++) {
        int row = bm + wm * 64 + mt * 16 + (lane >> 2);
#pragma unroll
        for (int nt = 0; nt < 8; nt++) {
            int col = bn + wn * 64 + nt * 8 + (lane & 3) * 2;
            *reinterpret_cast<float2*>(&C[(size_t)row * N + col]) =
                make_float2(acc[mt][nt][0], acc[mt][nt][1]);
            *reinterpret_cast<float2*>(&C[(size_t)(row + 8) * N + col]) =
                make_float2(acc[mt][nt][2], acc[mt][nt][3]);
        }
    }
}

// ---------------------------------------------------------------------------
// TF32 tensor-core causal flash attention (R4 inner loops, fused bf16 epilogue)
// CTA = (q-tile of 128, head, batch). 8 warps x 16 q-rows. TK=64 key tiles.
// ---------------------------------------------------------------------------
#define TQA   128
#define TKA   64
#define PADK  68
#define ATT_SMEM ((2 * 64 * PADK + 2 * 128 * PADK) * 4)   // 104448 bytes

__global__ __launch_bounds__(256, 2) void attn_tc_kernel()
{
    extern __shared__ float smf[];
    float* Ksm = smf;
    float* Vsm = smf + 64 * PADK;
    float* Qsm = smf + 2 * 64 * PADK;
    float* Psm = Qsm + 128 * PADK;

    const int tid  = threadIdx.x;
    const int lane = tid & 31;
    const int w    = tid >> 5;
    const int tr   = lane >> 2;      // 0..7
    const int tc   = lane & 3;       // 0..3

    const int qi = (int)gridDim.x - 1 - (int)blockIdx.x;   // big tiles first
    const int h  = blockIdx.y;
    const int b  = blockIdx.z;
    const int qb = qi * TQA;
    const size_t rowbase = (size_t)b * SEQ;

    const float* qptr = g_qkv + rowbase * D3 + h * HDIM;
    const float* kptr = qptr + EMBED;
    const float* vptr = qptr + 2 * EMBED;

    // Stage Q tile (128 x 64) into Qsm, pre-converted to tf32 bit patterns.
    for (int i = tid; i < 128 * 16; i += 256) {
        int r = i >> 4, c4 = (i & 15) * 4;
        float4 v = *reinterpret_cast<const float4*>(qptr + (size_t)(qb + r) * D3 + c4);
        float* dst = Qsm + r * PADK + c4;
        dst[0] = __uint_as_float(f2tf32(v.x));
        dst[1] = __uint_as_float(f2tf32(v.y));
        dst[2] = __uint_as_float(f2tf32(v.z));
        dst[3] = __uint_as_float(f2tf32(v.w));
    }

    const uint32_t ksb = smem_u32(Ksm);
    const uint32_t vsb = smem_u32(Vsm);

    float oacc[8][4];
#pragma unroll
    for (int nt = 0; nt < 8; nt++)
#pragma unroll
        for (int e = 0; e < 4; e++) oacc[nt][e] = 0.f;

    float m0 = -1e30f, m1 = -1e30f, l0 = 0.f, l1 = 0.f;

    const float CSC = 0.18033688f;   // (1/sqrt(64)) * log2(e)
    const int wrow  = qb + w * 16;
    const int gr0   = wrow + tr;
    const int jmax  = (qb + TQA - 1) / TKA;

    for (int j = 0; j <= jmax; j++) {
        const int kb = j * TKA;

        __syncthreads();   // previous tile's smem reads complete
#pragma unroll
        for (int rep = 0; rep < 4; rep++) {
            int i = tid + rep * 256;
            int r = i >> 4, c4 = (i & 15) * 4;
            uint32_t soff = (uint32_t)(r * PADK + c4) * 4;
            cp_async16(ksb + soff, kptr + (size_t)(kb + r) * D3 + c4);
            cp_async16(vsb + soff, vptr + (size_t)(kb + r) * D3 + c4);
        }
        cp_commit();
        cp_wait<0>();
        __syncthreads();

        if (kb <= wrow + 15) {
            // ---- S = Q @ K^T ----
            float sacc[8][4];
#pragma unroll
            for (int nt = 0; nt < 8; nt++)
#pragma unroll
                for (int e = 0; e < 4; e++) sacc[nt][e] = 0.f;

#pragma unroll
            for (int kt = 0; kt < 8; kt++) {
                uint32_t qa[4];
                const float* qrow = Qsm + (size_t)(w * 16 + tr) * PADK + kt * 8 + tc;
                qa[0] = __float_as_uint(qrow[0]);
                qa[1] = __float_as_uint(qrow[8 * PADK]);
                qa[2] = __float_as_uint(qrow[4]);
                qa[3] = __float_as_uint(qrow[8 * PADK + 4]);
#pragma unroll
                for (int nt = 0; nt < 8; nt++) {
                    uint32_t bb[2];
                    const float* krow = Ksm + (size_t)(nt * 8 + tr) * PADK + kt * 8 + tc;
                    bb[0] = f2tf32(krow[0]);
                    bb[1] = f2tf32(krow[4]);
                    mma_tf32(sacc[nt], qa, bb);
                }
            }

            // ---- online softmax ----
            const bool need_mask = (kb + TKA - 1) > wrow;
            float mx0 = -1e30f, mx1 = -1e30f;
#pragma unroll
            for (int nt = 0; nt < 8; nt++) {
                int c0 = kb + nt * 8 + 2 * tc;
                float z0 = sacc[nt][0] * CSC;
                float z1 = sacc[nt][1] * CSC;
                float z2 = sacc[nt][2] * CSC;
                float z3 = sacc[nt][3] * CSC;
                if (need_mask) {
                    if (c0     > gr0) z0 = -1e30f;
                    if (c0 + 1 > gr0) z1 = -1e30f;
                    if (c0     > gr0 + 8) z2 = -1e30f;
                    if (c0 + 1 > gr0 + 8) z3 = -1e30f;
                }
                sacc[nt][0] = z0; sacc[nt][1] = z1;
                sacc[nt][2] = z2; sacc[nt][3] = z3;
                mx0 = fmaxf(mx0, fmaxf(z0, z1));
                mx1 = fmaxf(mx1, fmaxf(z2, z3));
            }
            mx0 = fmaxf(mx0, __shfl_xor_sync(0xffffffffu, mx0, 1));
            mx0 = fmaxf(mx0, __shfl_xor_sync(0xffffffffu, mx0, 2));
            mx1 = fmaxf(mx1, __shfl_xor_sync(0xffffffffu, mx1, 1));
            mx1 = fmaxf(mx1, __shfl_xor_sync(0xffffffffu, mx1, 2));

            float m0n = fmaxf(m0, mx0);
            float m1n = fmaxf(m1, mx1);
            float f0 = exp2f(m0 - m0n);
            float f1 = exp2f(m1 - m1n);

            float sum0 = 0.f, sum1 = 0.f;
            float* prow0 = Psm + (size_t)(w * 16 + tr) * PADK + 2 * tc;
            float* prow1 = prow0 + 8 * PADK;
#pragma unroll
            for (int nt = 0; nt < 8; nt++) {
                float p00 = exp2f(sacc[nt][0] - m0n);
                float p01 = exp2f(sacc[nt][1] - m0n);
                float p10 = exp2f(sacc[nt][2] - m1n);
                float p11 = exp2f(sacc[nt][3] - m1n);
                sum0 += p00 + p01;
                sum1 += p10 + p11;
                *reinterpret_cast<float2*>(prow0 + nt * 8) =
                    make_float2(__uint_as_float(f2tf32(p00)), __uint_as_float(f2tf32(p01)));
                *reinterpret_cast<float2*>(prow1 + nt * 8) =
                    make_float2(__uint_as_float(f2tf32(p10)), __uint_as_float(f2tf32(p11)));
            }
            sum0 += __shfl_xor_sync(0xffffffffu, sum0, 1);
            sum0 += __shfl_xor_sync(0xffffffffu, sum0, 2);
            sum1 += __shfl_xor_sync(0xffffffffu, sum1, 1);
            sum1 += __shfl_xor_sync(0xffffffffu, sum1, 2);

            l0 = l0 * f0 + sum0;
            l1 = l1 * f1 + sum1;
            m0 = m0n; m1 = m1n;
#pragma unroll
            for (int nt = 0; nt < 8; nt++) {
                oacc[nt][0] *= f0; oacc[nt][1] *= f0;
                oacc[nt][2] *= f1; oacc[nt][3] *= f1;
            }

            __syncwarp();

            // ---- O += P @ V ----
#pragma unroll
            for (int kt = 0; kt < 8; kt++) {
                uint32_t pa[4];
                const float* prow = Psm + (size_t)(w * 16 + tr) * PADK + kt * 8 + tc;
                pa[0] = __float_as_uint(prow[0]);
                pa[1] = __float_as_uint(prow[8 * PADK]);
                pa[2] = __float_as_uint(prow[4]);
                pa[3] = __float_as_uint(prow[8 * PADK + 4]);
#pragma unroll
                for (int nt = 0; nt < 8; nt++) {
                    uint32_t vb[2];
                    const float* vrow = Vsm + (size_t)(kt * 8 + tc) * PADK + nt * 8 + tr;
                    vb[0] = f2tf32(vrow[0]);
                    vb[1] = f2tf32(vrow[4 * PADK]);
                    mma_tf32(oacc[nt], pa, vb);
                }
            }
        }
    }

    // Epilogue: normalize, split to bf16 hi/lo, write (fused split)
    float il0 = 1.0f / l0;
    float il1 = 1.0f / l1;
    size_t base0 = (size_t)(rowbase + gr0) * EMBED + h * HDIM + 2 * tc;
    size_t base1 = base0 + 8 * EMBED;
#pragma unroll
    for (int nt = 0; nt < 8; nt++) {
        float o00 = oacc[nt][0] * il0, o01 = oacc[nt][1] * il0;
        float o10 = oacc[nt][2] * il1, o11 = oacc[nt][3] * il1;
        __nv_bfloat16 h00 = __float2bfloat16(o00), h01 = __float2bfloat16(o01);
        __nv_bfloat16 h10 = __float2bfloat16(o10), h11 = __float2bfloat16(o11);
        *reinterpret_cast<__nv_bfloat162*>(&g_a_hi[base0 + nt * 8]) = __nv_bfloat162(h00, h01);
        *reinterpret_cast<__nv_bfloat162*>(&g_a_hi[base1 + nt * 8]) = __nv_bfloat162(h10, h11);
        *reinterpret_cast<__nv_bfloat162*>(&g_a_lo[base0 + nt * 8]) =
            __nv_bfloat162(__float2bfloat16(o00 - __bfloat162float(h00)),
                           __float2bfloat16(o01 - __bfloat162float(h01)));
        *reinterpret_cast<__nv_bfloat162*>(&g_a_lo[base1 + nt * 8]) =
            __nv_bfloat162(__float2bfloat16(o10 - __bfloat162float(h10)),
                           __float2bfloat16(o11 - __bfloat162float(h11)));
    }
}

// ---------------------------------------------------------------------------
// Launch
// ---------------------------------------------------------------------------
extern "C" void kernel_launch(void* const* d_in, const int* in_sizes, int n_in,
                              void* d_out, int out_size)
{
    const float* x     = (const float*)d_in[0];
    const float* qkv_w = (const float*)d_in[1];
    const float* out_w = (const float*)d_in[2];
    float* out = (float*)d_out;

    static bool attr_done = false;
    if (!attr_done) {
        cudaFuncSetAttribute(gemm3bf16_mma, cudaFuncAttributeMaxDynamicSharedMemorySize, GEMM_SMEM);
        cudaFuncSetAttribute(attn_tc_kernel, cudaFuncAttributeMaxDynamicSharedMemorySize, ATT_SMEM);
        attr_done = true;
    }

    __nv_bfloat16 *xh, *xl, *w1h, *w1l, *w2h, *w2l, *ah, *al;
    float *qkv;
    cudaGetSymbolAddress((void**)&xh,  g_x_hi);
    cudaGetSymbolAddress((void**)&xl,  g_x_lo);
    cudaGetSymbolAddress((void**)&w1h, g_w1_hi);
    cudaGetSymbolAddress((void**)&w1l, g_w1_lo);
    cudaGetSymbolAddress((void**)&w2h, g_w2_hi);
    cudaGetSymbolAddress((void**)&w2l, g_w2_lo);
    cudaGetSymbolAddress((void**)&ah,  g_a_hi);
    cudaGetSymbolAddress((void**)&al,  g_a_lo);
    cudaGetSymbolAddress((void**)&qkv, g_qkv);

    // 0) split inputs into bf16 hi/lo (float4 vectorized)
    {
        int n1 = MROWS * EMBED / 4;
        split4_kernel<<<(n1 + 255) / 256, 256>>>(x, xh, xl, n1);
        int n2 = D3 * EMBED / 4;
        split4_kernel<<<(n2 + 255) / 256, 256>>>(qkv_w, w1h, w1l, n2);
        int n3 = EMBED * EMBED / 4;
        split4_kernel<<<(n3 + 255) / 256, 256>>>(out_w, w2h, w2l, n3);
    }

    // 1) QKV projection
    {
        dim3 grid(D3 / 128, MROWS / 128);
        gemm3bf16_mma<<<grid, 128, GEMM_SMEM>>>(xh, xl, w1h, w1l, qkv, MROWS, D3, EMBED);
    }

    // 2) Causal flash attention (tf32 tensor cores, fused bf16 split epilogue)
    {
        dim3 grid(SEQ / TQA, NHEADS, BATCH);
        attn_tc_kernel<<<grid, 256, ATT_SMEM>>>();
    }

    // 3) out projection (reads fused-split attention output)
    {
        dim3 grid(EMBED / 128, MROWS / 128);
        gemm3bf16_mma<<<grid, 128, GEMM_SMEM>>>(ah, al, w2h, w2l, out, MROWS, EMBED, EMBED);
    }
}

// round 7
// speedup vs baseline: 1.1527x; 1.0187x over previous
#include <cuda_runtime.h>
#include <cuda_bf16.h>
#include <cstdint>

// Problem constants
#define BATCH   2
#define SEQ     2048
#define EMBED   1024
#define NHEADS  16
#define HDIM    64
#define D3      (3 * EMBED)          // 3072
#define MROWS   (BATCH * SEQ)        // 4096

// ---------------------------------------------------------------------------
// Scratch (static device globals: allocation-free per harness rules)
// ---------------------------------------------------------------------------
__device__ float g_qkv [(size_t)MROWS * D3];      // (4096, 3072)

__device__ __align__(16) __nv_bfloat16 g_x_hi [(size_t)MROWS * EMBED];
__device__ __align__(16) __nv_bfloat16 g_x_lo [(size_t)MROWS * EMBED];
__device__ __align__(16) __nv_bfloat16 g_w1_hi[(size_t)D3 * EMBED];
__device__ __align__(16) __nv_bfloat16 g_w1_lo[(size_t)D3 * EMBED];
__device__ __align__(16) __nv_bfloat16 g_w2_hi[(size_t)EMBED * EMBED];
__device__ __align__(16) __nv_bfloat16 g_w2_lo[(size_t)EMBED * EMBED];
__device__ __align__(16) __nv_bfloat16 g_a_hi [(size_t)MROWS * EMBED];
__device__ __align__(16) __nv_bfloat16 g_a_lo [(size_t)MROWS * EMBED];

// ---------------------------------------------------------------------------
// PTX helpers (base sm_103-legal: ldmatrix / mma.sync / cp.async only)
// ---------------------------------------------------------------------------
__device__ __forceinline__ uint32_t smem_u32(const void* p) {
    uint32_t a;
    asm("{ .reg .u64 t; cvta.to.shared.u64 t, %1; cvt.u32.u64 %0, t; }" : "=r"(a) : "l"(p));
    return a;
}
__device__ __forceinline__ void cp_async16(uint32_t dst, const void* src) {
    asm volatile("cp.async.cg.shared.global [%0], [%1], 16;" :: "r"(dst), "l"(src));
}
__device__ __forceinline__ void cp_commit() {
    asm volatile("cp.async.commit_group;" ::: "memory");
}
template <int N>
__device__ __forceinline__ void cp_wait() {
    asm volatile("cp.async.wait_group %0;" :: "n"(N) : "memory");
}
__device__ __forceinline__ void ldsm_x4(uint32_t* r, uint32_t addr) {
    asm volatile("ldmatrix.sync.aligned.m8n8.x4.shared.b16 {%0,%1,%2,%3}, [%4];"
                 : "=r"(r[0]), "=r"(r[1]), "=r"(r[2]), "=r"(r[3]) : "r"(addr));
}
__device__ __forceinline__ void mma_bf16(float* c, const uint32_t* a, const uint32_t* b) {
    asm volatile(
        "mma.sync.aligned.m16n8k16.row.col.f32.bf16.bf16.f32 "
        "{%0,%1,%2,%3}, {%4,%5,%6,%7}, {%8,%9}, {%0,%1,%2,%3};"
        : "+f"(c[0]), "+f"(c[1]), "+f"(c[2]), "+f"(c[3])
        : "r"(a[0]), "r"(a[1]), "r"(a[2]), "r"(a[3]), "r"(b[0]), "r"(b[1]));
}
__device__ __forceinline__ uint32_t f2tf32(float f) {
    uint32_t r;
    asm("cvt.rna.tf32.f32 %0, %1;" : "=r"(r) : "f"(f));
    return r;
}
__device__ __forceinline__ void mma_tf32(float* c, const uint32_t* a, const uint32_t* b) {
    asm volatile(
        "mma.sync.aligned.m16n8k8.row.col.f32.tf32.tf32.f32 "
        "{%0,%1,%2,%3}, {%4,%5,%6,%7}, {%8,%9}, {%0,%1,%2,%3};"
        : "+f"(c[0]), "+f"(c[1]), "+f"(c[2]), "+f"(c[3])
        : "r"(a[0]), "r"(a[1]), "r"(a[2]), "r"(a[3]), "r"(b[0]), "r"(b[1]));
}

// ---------------------------------------------------------------------------
// fp32 -> (hi, lo) bf16 split, float4-vectorized
// ---------------------------------------------------------------------------
__global__ void split4_kernel(const float* __restrict__ src,
                              __nv_bfloat16* __restrict__ hi,
                              __nv_bfloat16* __restrict__ lo, int n4)
{
    int i = blockIdx.x * blockDim.x + threadIdx.x;
    if (i >= n4) return;
    float4 v = reinterpret_cast<const float4*>(src)[i];
    __nv_bfloat16 h0 = __float2bfloat16(v.x);
    __nv_bfloat16 h1 = __float2bfloat16(v.y);
    __nv_bfloat16 h2 = __float2bfloat16(v.z);
    __nv_bfloat16 h3 = __float2bfloat16(v.w);
    __nv_bfloat162* hp = reinterpret_cast<__nv_bfloat162*>(hi);
    __nv_bfloat162* lp = reinterpret_cast<__nv_bfloat162*>(lo);
    hp[2 * i]     = __nv_bfloat162(h0, h1);
    hp[2 * i + 1] = __nv_bfloat162(h2, h3);
    lp[2 * i]     = __nv_bfloat162(__float2bfloat16(v.x - __bfloat162float(h0)),
                                   __float2bfloat16(v.y - __bfloat162float(h1)));
    lp[2 * i + 1] = __nv_bfloat162(__float2bfloat16(v.z - __bfloat162float(h2)),
                                   __float2bfloat16(v.w - __bfloat162float(h3)));
}

// ---------------------------------------------------------------------------
// 3xBF16 split GEMM via mma.sync (R6 config, unchanged):
// BM=BN=128, BK=32, 128 threads (4 warps), warp tile 64x64,
// 2-stage cp.async pipeline, 2 CTAs/SM.
// ---------------------------------------------------------------------------
#define GBK      32
#define ROWB     80
#define TILE_SB  (128 * ROWB)
#define STAGE_SB (4 * TILE_SB)            // 40960
#define GEMM_SMEM (2 * STAGE_SB)          // 81920

__device__ __forceinline__ void load_stage_mma(uint32_t sbase,
                                               const __nv_bfloat16* __restrict__ Ah,
                                               const __nv_bfloat16* __restrict__ Al,
                                               const __nv_bfloat16* __restrict__ Bh,
                                               const __nv_bfloat16* __restrict__ Bl,
                                               int bm, int bn, int K, int k0, int tid)
{
#pragma unroll
    for (int rep = 0; rep < 16; rep++) {
        const int t = rep >> 2;
        int e   = tid + (rep & 3) * 128;
        int row = e >> 2;
        int ch  = e & 3;
        const __nv_bfloat16* g = (t == 0) ? Ah : (t == 1) ? Al : (t == 2) ? Bh : Bl;
        int rbase = (t < 2) ? bm : bn;
        cp_async16(sbase + (uint32_t)t * TILE_SB + (uint32_t)(row * ROWB + ch * 16),
                   g + (size_t)(rbase + row) * K + k0 + ch * 8);
    }
}

__global__ __launch_bounds__(128, 2) void gemm3bf16_mma(
    const __nv_bfloat16* __restrict__ Ah, const __nv_bfloat16* __restrict__ Al,
    const __nv_bfloat16* __restrict__ Bh, const __nv_bfloat16* __restrict__ Bl,
    float* __restrict__ C, int M, int N, int K)
{
    extern __shared__ __align__(16) char dynsmem[];
    const uint32_t sb = smem_u32(dynsmem);

    const int tid  = threadIdx.x;
    const int lane = tid & 31;
    const int wid  = tid >> 5;
    const int wm   = wid >> 1;
    const int wn   = wid & 1;
    const int bm   = blockIdx.y * 128;
    const int bn   = blockIdx.x * 128;

    float acc[4][8][4];
#pragma unroll
    for (int i = 0; i < 4; i++)
#pragma unroll
        for (int j = 0; j < 8; j++)
#pragma unroll
            for (int k = 0; k < 4; k++) acc[i][j][k] = 0.f;

    const int NIT = K / GBK;

    load_stage_mma(sb, Ah, Al, Bh, Bl, bm, bn, K, 0, tid);
    cp_commit();

    const uint32_t a_row_in = (uint32_t)(lane & 15);
    const uint32_t a_kb     = (uint32_t)((lane >> 4) * 16);
    const int g  = lane >> 3;
    const int br = lane & 7;
    const uint32_t b_row_in = (uint32_t)(((g >> 1) * 8) + br);
    const uint32_t b_kb     = (uint32_t)((g & 1) * 16);

    for (int it = 0; it < NIT; it++) {
        if (it + 1 < NIT) {
            load_stage_mma(sb + (uint32_t)((it + 1) & 1) * STAGE_SB,
                           Ah, Al, Bh, Bl, bm, bn, K, (it + 1) * GBK, tid);
            cp_commit();
            cp_wait<1>();
        } else {
            cp_wait<0>();
        }
        __syncthreads();

        const uint32_t st = sb + (uint32_t)(it & 1) * STAGE_SB;

#pragma unroll
        for (int ks = 0; ks < 2; ks++) {
            const uint32_t kb = (uint32_t)(ks * 32);

            uint32_t ah[4][4], al[4][4];
#pragma unroll
            for (int mt = 0; mt < 4; mt++) {
                uint32_t addr = st + (uint32_t)((wm * 64 + mt * 16) + a_row_in) * ROWB + kb + a_kb;
                ldsm_x4(ah[mt], addr);
                ldsm_x4(al[mt], addr + TILE_SB);
            }

#pragma unroll
            for (int bt = 0; bt < 4; bt++) {
                uint32_t addr = st + 2 * TILE_SB +
                                (uint32_t)((wn * 64 + bt * 16) + b_row_in) * ROWB + kb + b_kb;
                uint32_t th[4], tl[4];
                ldsm_x4(th, addr);
                ldsm_x4(tl, addr + TILE_SB);
#pragma unroll
                for (int mt = 0; mt < 4; mt++) {
                    mma_bf16(acc[mt][2 * bt],     ah[mt], th);
                    mma_bf16(acc[mt][2 * bt],     ah[mt], tl);
                    mma_bf16(acc[mt][2 * bt],     al[mt], th);
                    mma_bf16(acc[mt][2 * bt + 1], ah[mt], th + 2);
                    mma_bf16(acc[mt][2 * bt + 1], ah[mt], tl + 2);
                    mma_bf16(acc[mt][2 * bt + 1], al[mt], th + 2);
                }
            }
        }
        __syncthreads();
    }

#pragma unroll
    for (int mt = 0; mt < 4; mt++) {
        int row = bm + wm * 64 + mt * 16 + (lane >> 2);
#pragma unroll
        for (int nt = 0; nt < 8; nt++) {
            int col = bn + wn * 64 + nt * 8 + (lane & 3) * 2;
            *reinterpret_cast<float2*>(&C[(size_t)row * N + col]) =
                make_float2(acc[mt][nt][0], acc[mt][nt][1]);
            *reinterpret_cast<float2*>(&C[(size_t)(row + 8) * N + col]) =
                make_float2(acc[mt][nt][2], acc[mt][nt][3]);
        }
    }
}

// ---------------------------------------------------------------------------
// TF32 tensor-core causal flash attention v2:
//  - Q fragments hoisted to registers (loop-invariant)
//  - K/V double-buffered via cp.async (2 stages)
//  - 1 CTA/SM, 256 threads, 8 warps x 16 q-rows, TK=64
// smem: KV[2 stages][K|V][64][PADK] fp32  |  Psm[128][PADK] (also Q staging)
// ---------------------------------------------------------------------------
#define TQA   128
#define TKA   64
#define PADK  68
#define KVT_F  (64 * PADK)                 // floats per K or V tile
#define STG_F  (2 * KVT_F)                 // floats per stage (K+V)
#define ATT_SMEM ((2 * STG_F + 128 * PADK) * 4)   // 104448 bytes

__global__ __launch_bounds__(256, 1) void attn_tc_kernel()
{
    extern __shared__ float smf[];
    float* Psm = smf + 2 * STG_F;          // P buffer; also Q staging

    const int tid  = threadIdx.x;
    const int lane = tid & 31;
    const int w    = tid >> 5;
    const int tr   = lane >> 2;      // 0..7
    const int tc   = lane & 3;       // 0..3

    const int qi = (int)gridDim.x - 1 - (int)blockIdx.x;   // big tiles first
    const int h  = blockIdx.y;
    const int b  = blockIdx.z;
    const int qb = qi * TQA;
    const size_t rowbase = (size_t)b * SEQ;

    const float* qptr = g_qkv + rowbase * D3 + h * HDIM;
    const float* kptr = qptr + EMBED;
    const float* vptr = qptr + 2 * EMBED;

    // Stage Q tile (128 x 64) into Psm (raw fp32)
    for (int i = tid; i < 128 * 16; i += 256) {
        int r = i >> 4, c4 = (i & 15) * 4;
        float4 v = *reinterpret_cast<const float4*>(qptr + (size_t)(qb + r) * D3 + c4);
        float* dst = Psm + r * PADK + c4;
        dst[0] = v.x; dst[1] = v.y; dst[2] = v.z; dst[3] = v.w;
    }
    __syncthreads();

    // Extract loop-invariant Q fragments into registers (tf32)
    uint32_t qfrag[8][4];
    {
        const float* qrow = Psm + (size_t)(w * 16 + tr) * PADK + tc;
#pragma unroll
        for (int kt = 0; kt < 8; kt++) {
            qfrag[kt][0] = f2tf32(qrow[kt * 8]);
            qfrag[kt][1] = f2tf32(qrow[8 * PADK + kt * 8]);
            qfrag[kt][2] = f2tf32(qrow[kt * 8 + 4]);
            qfrag[kt][3] = f2tf32(qrow[8 * PADK + kt * 8 + 4]);
        }
    }
    __syncthreads();   // Q staging reads done; Psm free for P

    const uint32_t s0 = smem_u32(smf);

    float oacc[8][4];
#pragma unroll
    for (int nt = 0; nt < 8; nt++)
#pragma unroll
        for (int e = 0; e < 4; e++) oacc[nt][e] = 0.f;

    float m0 = -1e30f, m1 = -1e30f, l0 = 0.f, l1 = 0.f;

    const float CSC = 0.18033688f;   // (1/sqrt(64)) * log2(e)
    const int wrow  = qb + w * 16;
    const int gr0   = wrow + tr;
    const int jmax  = (qb + TQA - 1) / TKA;

    // prologue: issue K/V loads for tile 0 into stage 0
#pragma unroll
    for (int rep = 0; rep < 4; rep++) {
        int i = tid + rep * 256;
        int r = i >> 4, c4 = (i & 15) * 4;
        uint32_t soff = (uint32_t)(r * PADK + c4) * 4;
        cp_async16(s0 + soff,                 kptr + (size_t)r * D3 + c4);
        cp_async16(s0 + KVT_F * 4 + soff,     vptr + (size_t)r * D3 + c4);
    }
    cp_commit();

    for (int j = 0; j <= jmax; j++) {
        const int kb = j * TKA;

        if (j < jmax) {
            const int kb1 = (j + 1) * TKA;
            const uint32_t sst = s0 + (uint32_t)(((j + 1) & 1) * STG_F) * 4;
#pragma unroll
            for (int rep = 0; rep < 4; rep++) {
                int i = tid + rep * 256;
                int r = i >> 4, c4 = (i & 15) * 4;
                uint32_t soff = (uint32_t)(r * PADK + c4) * 4;
                cp_async16(sst + soff,             kptr + (size_t)(kb1 + r) * D3 + c4);
                cp_async16(sst + KVT_F * 4 + soff, vptr + (size_t)(kb1 + r) * D3 + c4);
            }
            cp_commit();
            cp_wait<1>();
        } else {
            cp_wait<0>();
        }
        __syncthreads();

        const float* Ksm = smf + (j & 1) * STG_F;
        const float* Vsm = Ksm + KVT_F;

        if (kb <= wrow + 15) {
            // ---- S = Q @ K^T ----
            float sacc[8][4];
#pragma unroll
            for (int nt = 0; nt < 8; nt++)
#pragma unroll
                for (int e = 0; e < 4; e++) sacc[nt][e] = 0.f;

#pragma unroll
            for (int kt = 0; kt < 8; kt++) {
#pragma unroll
                for (int nt = 0; nt < 8; nt++) {
                    uint32_t bb[2];
                    const float* krow = Ksm + (size_t)(nt * 8 + tr) * PADK + kt * 8 + tc;
                    bb[0] = f2tf32(krow[0]);
                    bb[1] = f2tf32(krow[4]);
                    mma_tf32(sacc[nt], qfrag[kt], bb);
                }
            }

            // ---- online softmax ----
            const bool need_mask = (kb + TKA - 1) > wrow;
            float mx0 = -1e30f, mx1 = -1e30f;
#pragma unroll
            for (int nt = 0; nt < 8; nt++) {
                int c0 = kb + nt * 8 + 2 * tc;
                float z0 = sacc[nt][0] * CSC;
                float z1 = sacc[nt][1] * CSC;
                float z2 = sacc[nt][2] * CSC;
                float z3 = sacc[nt][3] * CSC;
                if (need_mask) {
                    if (c0     > gr0) z0 = -1e30f;
                    if (c0 + 1 > gr0) z1 = -1e30f;
                    if (c0     > gr0 + 8) z2 = -1e30f;
                    if (c0 + 1 > gr0 + 8) z3 = -1e30f;
                }
                sacc[nt][0] = z0; sacc[nt][1] = z1;
                sacc[nt][2] = z2; sacc[nt][3] = z3;
                mx0 = fmaxf(mx0, fmaxf(z0, z1));
                mx1 = fmaxf(mx1, fmaxf(z2, z3));
            }
            mx0 = fmaxf(mx0, __shfl_xor_sync(0xffffffffu, mx0, 1));
            mx0 = fmaxf(mx0, __shfl_xor_sync(0xffffffffu, mx0, 2));
            mx1 = fmaxf(mx1, __shfl_xor_sync(0xffffffffu, mx1, 1));
            mx1 = fmaxf(mx1, __shfl_xor_sync(0xffffffffu, mx1, 2));

            float m0n = fmaxf(m0, mx0);
            float m1n = fmaxf(m1, mx1);
            float f0 = exp2f(m0 - m0n);
            float f1 = exp2f(m1 - m1n);

            float sum0 = 0.f, sum1 = 0.f;
            float* prow0 = Psm + (size_t)(w * 16 + tr) * PADK + 2 * tc;
            float* prow1 = prow0 + 8 * PADK;
#pragma unroll
            for (int nt = 0; nt < 8; nt++) {
                float p00 = exp2f(sacc[nt][0] - m0n);
                float p01 = exp2f(sacc[nt][1] - m0n);
                float p10 = exp2f(sacc[nt][2] - m1n);
                float p11 = exp2f(sacc[nt][3] - m1n);
                sum0 += p00 + p01;
                sum1 += p10 + p11;
                *reinterpret_cast<float2*>(prow0 + nt * 8) =
                    make_float2(__uint_as_float(f2tf32(p00)), __uint_as_float(f2tf32(p01)));
                *reinterpret_cast<float2*>(prow1 + nt * 8) =
                    make_float2(__uint_as_float(f2tf32(p10)), __uint_as_float(f2tf32(p11)));
            }
            sum0 += __shfl_xor_sync(0xffffffffu, sum0, 1);
            sum0 += __shfl_xor_sync(0xffffffffu, sum0, 2);
            sum1 += __shfl_xor_sync(0xffffffffu, sum1, 1);
            sum1 += __shfl_xor_sync(0xffffffffu, sum1, 2);

            l0 = l0 * f0 + sum0;
            l1 = l1 * f1 + sum1;
            m0 = m0n; m1 = m1n;
#pragma unroll
            for (int nt = 0; nt < 8; nt++) {
                oacc[nt][0] *= f0; oacc[nt][1] *= f0;
                oacc[nt][2] *= f1; oacc[nt][3] *= f1;
            }

            __syncwarp();

            // ---- O += P @ V ----
#pragma unroll
            for (int kt = 0; kt < 8; kt++) {
                uint32_t pa[4];
                const float* prow = Psm + (size_t)(w * 16 + tr) * PADK + kt * 8 + tc;
                pa[0] = __float_as_uint(prow[0]);
                pa[1] = __float_as_uint(prow[8 * PADK]);
                pa[2] = __float_as_uint(prow[4]);
                pa[3] = __float_as_uint(prow[8 * PADK + 4]);
#pragma unroll
                for (int nt = 0; nt < 8; nt++) {
                    uint32_t vb[2];
                    const float* vrow = Vsm + (size_t)(kt * 8 + tc) * PADK + nt * 8 + tr;
                    vb[0] = f2tf32(vrow[0]);
                    vb[1] = f2tf32(vrow[4 * PADK]);
                    mma_tf32(oacc[nt], pa, vb);
                }
            }
        }
        __syncthreads();   // all compute on this stage done before it is reloaded
    }

    // Epilogue: normalize, split to bf16 hi/lo, write (fused split)
    float il0 = 1.0f / l0;
    float il1 = 1.0f / l1;
    size_t base0 = (size_t)(rowbase + gr0) * EMBED + h * HDIM + 2 * tc;
    size_t base1 = base0 + 8 * EMBED;
#pragma unroll
    for (int nt = 0; nt < 8; nt++) {
        float o00 = oacc[nt][0] * il0, o01 = oacc[nt][1] * il0;
        float o10 = oacc[nt][2] * il1, o11 = oacc[nt][3] * il1;
        __nv_bfloat16 h00 = __float2bfloat16(o00), h01 = __float2bfloat16(o01);
        __nv_bfloat16 h10 = __float2bfloat16(o10), h11 = __float2bfloat16(o11);
        *reinterpret_cast<__nv_bfloat162*>(&g_a_hi[base0 + nt * 8]) = __nv_bfloat162(h00, h01);
        *reinterpret_cast<__nv_bfloat162*>(&g_a_hi[base1 + nt * 8]) = __nv_bfloat162(h10, h11);
        *reinterpret_cast<__nv_bfloat162*>(&g_a_lo[base0 + nt * 8]) =
            __nv_bfloat162(__float2bfloat16(o00 - __bfloat162float(h00)),
                           __float2bfloat16(o01 - __bfloat162float(h01)));
        *reinterpret_cast<__nv_bfloat162*>(&g_a_lo[base1 + nt * 8]) =
            __nv_bfloat162(__float2bfloat16(o10 - __bfloat162float(h10)),
                           __float2bfloat16(o11 - __bfloat162float(h11)));
    }
}

// ---------------------------------------------------------------------------
// Launch
// ---------------------------------------------------------------------------
extern "C" void kernel_launch(void* const* d_in, const int* in_sizes, int n_in,
                              void* d_out, int out_size)
{
    const float* x     = (const float*)d_in[0];
    const float* qkv_w = (const float*)d_in[1];
    const float* out_w = (const float*)d_in[2];
    float* out = (float*)d_out;

    static bool attr_done = false;
    if (!attr_done) {
        cudaFuncSetAttribute(gemm3bf16_mma, cudaFuncAttributeMaxDynamicSharedMemorySize, GEMM_SMEM);
        cudaFuncSetAttribute(attn_tc_kernel, cudaFuncAttributeMaxDynamicSharedMemorySize, ATT_SMEM);
        attr_done = true;
    }

    __nv_bfloat16 *xh, *xl, *w1h, *w1l, *w2h, *w2l, *ah, *al;
    float *qkv;
    cudaGetSymbolAddress((void**)&xh,  g_x_hi);
    cudaGetSymbolAddress((void**)&xl,  g_x_lo);
    cudaGetSymbolAddress((void**)&w1h, g_w1_hi);
    cudaGetSymbolAddress((void**)&w1l, g_w1_lo);
    cudaGetSymbolAddress((void**)&w2h, g_w2_hi);
    cudaGetSymbolAddress((void**)&w2l, g_w2_lo);
    cudaGetSymbolAddress((void**)&ah,  g_a_hi);
    cudaGetSymbolAddress((void**)&al,  g_a_lo);
    cudaGetSymbolAddress((void**)&qkv, g_qkv);

    // 0) split inputs into bf16 hi/lo (float4 vectorized)
    {
        int n1 = MROWS * EMBED / 4;
        split4_kernel<<<(n1 + 255) / 256, 256>>>(x, xh, xl, n1);
        int n2 = D3 * EMBED / 4;
        split4_kernel<<<(n2 + 255) / 256, 256>>>(qkv_w, w1h, w1l, n2);
        int n3 = EMBED * EMBED / 4;
        split4_kernel<<<(n3 + 255) / 256, 256>>>(out_w, w2h, w2l, n3);
    }

    // 1) QKV projection
    {
        dim3 grid(D3 / 128, MROWS / 128);
        gemm3bf16_mma<<<grid, 128, GEMM_SMEM>>>(xh, xl, w1h, w1l, qkv, MROWS, D3, EMBED);
    }

    // 2) Causal flash attention (tf32 tensor cores, pipelined K/V, fused split)
    {
        dim3 grid(SEQ / TQA, NHEADS, BATCH);
        attn_tc_kernel<<<grid, 256, ATT_SMEM>>>();
    }

    // 3) out projection (reads fused-split attention output)
    {
        dim3 grid(EMBED / 128, MROWS / 128);
        gemm3bf16_mma<<<grid, 128, GEMM_SMEM>>>(ah, al, w2h, w2l, out, MROWS, EMBED, EMBED);
    }
}

// round 8
// speedup vs baseline: 1.1941x; 1.0359x over previous
#include <cuda_runtime.h>
#include <cuda_bf16.h>
#include <cstdint>

// Problem constants
#define BATCH   2
#define SEQ     2048
#define EMBED   1024
#define NHEADS  16
#define HDIM    64
#define D3      (3 * EMBED)          // 3072
#define MROWS   (BATCH * SEQ)        // 4096

// ---------------------------------------------------------------------------
// Scratch (static device globals: allocation-free per harness rules)
// ---------------------------------------------------------------------------
__device__ float g_qkv [(size_t)MROWS * D3];      // (4096, 3072)

__device__ __align__(16) __nv_bfloat16 g_x_hi [(size_t)MROWS * EMBED];
__device__ __align__(16) __nv_bfloat16 g_x_lo [(size_t)MROWS * EMBED];
__device__ __align__(16) __nv_bfloat16 g_w1_hi[(size_t)D3 * EMBED];
__device__ __align__(16) __nv_bfloat16 g_w1_lo[(size_t)D3 * EMBED];
__device__ __align__(16) __nv_bfloat16 g_w2_hi[(size_t)EMBED * EMBED];
__device__ __align__(16) __nv_bfloat16 g_w2_lo[(size_t)EMBED * EMBED];
__device__ __align__(16) __nv_bfloat16 g_a_hi [(size_t)MROWS * EMBED];
__device__ __align__(16) __nv_bfloat16 g_a_lo [(size_t)MROWS * EMBED];

// ---------------------------------------------------------------------------
// PTX helpers (base sm_103-legal: ldmatrix / mma.sync / cp.async only)
// ---------------------------------------------------------------------------
__device__ __forceinline__ uint32_t smem_u32(const void* p) {
    uint32_t a;
    asm("{ .reg .u64 t; cvta.to.shared.u64 t, %1; cvt.u32.u64 %0, t; }" : "=r"(a) : "l"(p));
    return a;
}
__device__ __forceinline__ void cp_async16(uint32_t dst, const void* src) {
    asm volatile("cp.async.cg.shared.global [%0], [%1], 16;" :: "r"(dst), "l"(src));
}
__device__ __forceinline__ void cp_commit() {
    asm volatile("cp.async.commit_group;" ::: "memory");
}
template <int N>
__device__ __forceinline__ void cp_wait() {
    asm volatile("cp.async.wait_group %0;" :: "n"(N) : "memory");
}
__device__ __forceinline__ void ldsm_x4(uint32_t* r, uint32_t addr) {
    asm volatile("ldmatrix.sync.aligned.m8n8.x4.shared.b16 {%0,%1,%2,%3}, [%4];"
                 : "=r"(r[0]), "=r"(r[1]), "=r"(r[2]), "=r"(r[3]) : "r"(addr));
}
__device__ __forceinline__ void mma_bf16(float* c, const uint32_t* a, const uint32_t* b) {
    asm volatile(
        "mma.sync.aligned.m16n8k16.row.col.f32.bf16.bf16.f32 "
        "{%0,%1,%2,%3}, {%4,%5,%6,%7}, {%8,%9}, {%0,%1,%2,%3};"
        : "+f"(c[0]), "+f"(c[1]), "+f"(c[2]), "+f"(c[3])
        : "r"(a[0]), "r"(a[1]), "r"(a[2]), "r"(a[3]), "r"(b[0]), "r"(b[1]));
}
__device__ __forceinline__ uint32_t f2tf32(float f) {
    uint32_t r;
    asm("cvt.rna.tf32.f32 %0, %1;" : "=r"(r) : "f"(f));
    return r;
}
__device__ __forceinline__ void mma_tf32(float* c, const uint32_t* a, const uint32_t* b) {
    asm volatile(
        "mma.sync.aligned.m16n8k8.row.col.f32.tf32.tf32.f32 "
        "{%0,%1,%2,%3}, {%4,%5,%6,%7}, {%8,%9}, {%0,%1,%2,%3};"
        : "+f"(c[0]), "+f"(c[1]), "+f"(c[2]), "+f"(c[3])
        : "r"(a[0]), "r"(a[1]), "r"(a[2]), "r"(a[3]), "r"(b[0]), "r"(b[1]));
}

// ---------------------------------------------------------------------------
// fp32 -> (hi, lo) bf16 split, float4-vectorized
// ---------------------------------------------------------------------------
__global__ void split4_kernel(const float* __restrict__ src,
                              __nv_bfloat16* __restrict__ hi,
                              __nv_bfloat16* __restrict__ lo, int n4)
{
    int i = blockIdx.x * blockDim.x + threadIdx.x;
    if (i >= n4) return;
    float4 v = reinterpret_cast<const float4*>(src)[i];
    __nv_bfloat16 h0 = __float2bfloat16(v.x);
    __nv_bfloat16 h1 = __float2bfloat16(v.y);
    __nv_bfloat16 h2 = __float2bfloat16(v.z);
    __nv_bfloat16 h3 = __float2bfloat16(v.w);
    __nv_bfloat162* hp = reinterpret_cast<__nv_bfloat162*>(hi);
    __nv_bfloat162* lp = reinterpret_cast<__nv_bfloat162*>(lo);
    hp[2 * i]     = __nv_bfloat162(h0, h1);
    hp[2 * i + 1] = __nv_bfloat162(h2, h3);
    lp[2 * i]     = __nv_bfloat162(__float2bfloat16(v.x - __bfloat162float(h0)),
                                   __float2bfloat16(v.y - __bfloat162float(h1)));
    lp[2 * i + 1] = __nv_bfloat162(__float2bfloat16(v.z - __bfloat162float(h2)),
                                   __float2bfloat16(v.w - __bfloat162float(h3)));
}

// ---------------------------------------------------------------------------
// 3xBF16 split GEMM via mma.sync (R6 config, unchanged):
// BM=BN=128, BK=32, 128 threads (4 warps), warp tile 64x64,
// 2-stage cp.async pipeline, 2 CTAs/SM.
// ---------------------------------------------------------------------------
#define GBK      32
#define ROWB     80
#define TILE_SB  (128 * ROWB)
#define STAGE_SB (4 * TILE_SB)            // 40960
#define GEMM_SMEM (2 * STAGE_SB)          // 81920

__device__ __forceinline__ void load_stage_mma(uint32_t sbase,
                                               const __nv_bfloat16* __restrict__ Ah,
                                               const __nv_bfloat16* __restrict__ Al,
                                               const __nv_bfloat16* __restrict__ Bh,
                                               const __nv_bfloat16* __restrict__ Bl,
                                               int bm, int bn, int K, int k0, int tid)
{
#pragma unroll
    for (int rep = 0; rep < 16; rep++) {
        const int t = rep >> 2;
        int e   = tid + (rep & 3) * 128;
        int row = e >> 2;
        int ch  = e & 3;
        const __nv_bfloat16* g = (t == 0) ? Ah : (t == 1) ? Al : (t == 2) ? Bh : Bl;
        int rbase = (t < 2) ? bm : bn;
        cp_async16(sbase + (uint32_t)t * TILE_SB + (uint32_t)(row * ROWB + ch * 16),
                   g + (size_t)(rbase + row) * K + k0 + ch * 8);
    }
}

__global__ __launch_bounds__(128, 2) void gemm3bf16_mma(
    const __nv_bfloat16* __restrict__ Ah, const __nv_bfloat16* __restrict__ Al,
    const __nv_bfloat16* __restrict__ Bh, const __nv_bfloat16* __restrict__ Bl,
    float* __restrict__ C, int M, int N, int K)
{
    extern __shared__ __align__(16) char dynsmem[];
    const uint32_t sb = smem_u32(dynsmem);

    const int tid  = threadIdx.x;
    const int lane = tid & 31;
    const int wid  = tid >> 5;
    const int wm   = wid >> 1;
    const int wn   = wid & 1;
    const int bm   = blockIdx.y * 128;
    const int bn   = blockIdx.x * 128;

    float acc[4][8][4];
#pragma unroll
    for (int i = 0; i < 4; i++)
#pragma unroll
        for (int j = 0; j < 8; j++)
#pragma unroll
            for (int k = 0; k < 4; k++) acc[i][j][k] = 0.f;

    const int NIT = K / GBK;

    load_stage_mma(sb, Ah, Al, Bh, Bl, bm, bn, K, 0, tid);
    cp_commit();

    const uint32_t a_row_in = (uint32_t)(lane & 15);
    const uint32_t a_kb     = (uint32_t)((lane >> 4) * 16);
    const int g  = lane >> 3;
    const int br = lane & 7;
    const uint32_t b_row_in = (uint32_t)(((g >> 1) * 8) + br);
    const uint32_t b_kb     = (uint32_t)((g & 1) * 16);

    for (int it = 0; it < NIT; it++) {
        if (it + 1 < NIT) {
            load_stage_mma(sb + (uint32_t)((it + 1) & 1) * STAGE_SB,
                           Ah, Al, Bh, Bl, bm, bn, K, (it + 1) * GBK, tid);
            cp_commit();
            cp_wait<1>();
        } else {
            cp_wait<0>();
        }
        __syncthreads();

        const uint32_t st = sb + (uint32_t)(it & 1) * STAGE_SB;

#pragma unroll
        for (int ks = 0; ks < 2; ks++) {
            const uint32_t kb = (uint32_t)(ks * 32);

            uint32_t ah[4][4], al[4][4];
#pragma unroll
            for (int mt = 0; mt < 4; mt++) {
                uint32_t addr = st + (uint32_t)((wm * 64 + mt * 16) + a_row_in) * ROWB + kb + a_kb;
                ldsm_x4(ah[mt], addr);
                ldsm_x4(al[mt], addr + TILE_SB);
            }

#pragma unroll
            for (int bt = 0; bt < 4; bt++) {
                uint32_t addr = st + 2 * TILE_SB +
                                (uint32_t)((wn * 64 + bt * 16) + b_row_in) * ROWB + kb + b_kb;
                uint32_t th[4], tl[4];
                ldsm_x4(th, addr);
                ldsm_x4(tl, addr + TILE_SB);
#pragma unroll
                for (int mt = 0; mt < 4; mt++) {
                    mma_bf16(acc[mt][2 * bt],     ah[mt], th);
                    mma_bf16(acc[mt][2 * bt],     ah[mt], tl);
                    mma_bf16(acc[mt][2 * bt],     al[mt], th);
                    mma_bf16(acc[mt][2 * bt + 1], ah[mt], th + 2);
                    mma_bf16(acc[mt][2 * bt + 1], ah[mt], tl + 2);
                    mma_bf16(acc[mt][2 * bt + 1], al[mt], th + 2);
                }
            }
        }
        __syncthreads();
    }

#pragma unroll
    for (int mt = 0; mt < 4; mt++) {
        int row = bm + wm * 64 + mt * 16 + (lane >> 2);
#pragma unroll
        for (int nt = 0; nt < 8; nt++) {
            int col = bn + wn * 64 + nt * 8 + (lane & 3) * 2;
            *reinterpret_cast<float2*>(&C[(size_t)row * N + col]) =
                make_float2(acc[mt][nt][0], acc[mt][nt][1]);
            *reinterpret_cast<float2*>(&C[(size_t)(row + 8) * N + col]) =
                make_float2(acc[mt][nt][2], acc[mt][nt][3]);
        }
    }
}

// ---------------------------------------------------------------------------
// TF32 tensor-core causal flash attention v3:
//  - Q fragments in registers (loop-invariant)
//  - K/V double-buffered via cp.async (2 stages)
//  - P kept in REGISTERS: C-fragment -> A-fragment fixup via intra-quad shfl
//    (no P smem round-trip; smem traffic is K/V fragments only)
//  - 1 CTA/SM, 256 threads, 8 warps x 16 q-rows, TK=64
// smem: KV[2 stages][K|V][64][PADK] fp32 (Q staged through stage 0 first)
// ---------------------------------------------------------------------------
#define TQA   128
#define TKA   64
#define PADK  68
#define KVT_F  (64 * PADK)                 // floats per K or V tile
#define STG_F  (2 * KVT_F)                 // floats per stage (K+V)
#define ATT_SMEM (2 * STG_F * 4)           // 69632 bytes

__global__ __launch_bounds__(256, 1) void attn_tc_kernel()
{
    extern __shared__ float smf[];

    const int tid  = threadIdx.x;
    const int lane = tid & 31;
    const int w    = tid >> 5;
    const int tr   = lane >> 2;      // 0..7
    const int tc   = lane & 3;       // 0..3

    const int qi = (int)gridDim.x - 1 - (int)blockIdx.x;   // big tiles first
    const int h  = blockIdx.y;
    const int b  = blockIdx.z;
    const int qb = qi * TQA;
    const size_t rowbase = (size_t)b * SEQ;

    const float* qptr = g_qkv + rowbase * D3 + h * HDIM;
    const float* kptr = qptr + EMBED;
    const float* vptr = qptr + 2 * EMBED;

    // Stage Q tile (128 x 64) through stage-0 smem (raw fp32), then to regs.
    for (int i = tid; i < 128 * 16; i += 256) {
        int r = i >> 4, c4 = (i & 15) * 4;
        float4 v = *reinterpret_cast<const float4*>(qptr + (size_t)(qb + r) * D3 + c4);
        float* dst = smf + r * PADK + c4;
        dst[0] = v.x; dst[1] = v.y; dst[2] = v.z; dst[3] = v.w;
    }
    __syncthreads();

    uint32_t qfrag[8][4];
    {
        const float* qrow = smf + (size_t)(w * 16 + tr) * PADK + tc;
#pragma unroll
        for (int kt = 0; kt < 8; kt++) {
            qfrag[kt][0] = f2tf32(qrow[kt * 8]);
            qfrag[kt][1] = f2tf32(qrow[8 * PADK + kt * 8]);
            qfrag[kt][2] = f2tf32(qrow[kt * 8 + 4]);
            qfrag[kt][3] = f2tf32(qrow[8 * PADK + kt * 8 + 4]);
        }
    }
    __syncthreads();   // Q staging reads done; smem free for K/V stages

    const uint32_t s0 = smem_u32(smf);

    float oacc[8][4];
#pragma unroll
    for (int nt = 0; nt < 8; nt++)
#pragma unroll
        for (int e = 0; e < 4; e++) oacc[nt][e] = 0.f;

    float m0 = -1e30f, m1 = -1e30f, l0 = 0.f, l1 = 0.f;

    const float CSC = 0.18033688f;   // (1/sqrt(64)) * log2(e)
    const int wrow  = qb + w * 16;
    const int gr0   = wrow + tr;
    const int jmax  = (qb + TQA - 1) / TKA;

    // prologue: issue K/V loads for tile 0 into stage 0
#pragma unroll
    for (int rep = 0; rep < 4; rep++) {
        int i = tid + rep * 256;
        int r = i >> 4, c4 = (i & 15) * 4;
        uint32_t soff = (uint32_t)(r * PADK + c4) * 4;
        cp_async16(s0 + soff,             kptr + (size_t)r * D3 + c4);
        cp_async16(s0 + KVT_F * 4 + soff, vptr + (size_t)r * D3 + c4);
    }
    cp_commit();

    for (int j = 0; j <= jmax; j++) {
        const int kb = j * TKA;

        if (j < jmax) {
            const int kb1 = (j + 1) * TKA;
            const uint32_t sst = s0 + (uint32_t)(((j + 1) & 1) * STG_F) * 4;
#pragma unroll
            for (int rep = 0; rep < 4; rep++) {
                int i = tid + rep * 256;
                int r = i >> 4, c4 = (i & 15) * 4;
                uint32_t soff = (uint32_t)(r * PADK + c4) * 4;
                cp_async16(sst + soff,             kptr + (size_t)(kb1 + r) * D3 + c4);
                cp_async16(sst + KVT_F * 4 + soff, vptr + (size_t)(kb1 + r) * D3 + c4);
            }
            cp_commit();
            cp_wait<1>();
        } else {
            cp_wait<0>();
        }
        __syncthreads();

        const float* Ksm = smf + (j & 1) * STG_F;
        const float* Vsm = Ksm + KVT_F;

        if (kb <= wrow + 15) {
            // ---- S = Q @ K^T ----
            float sacc[8][4];
#pragma unroll
            for (int nt = 0; nt < 8; nt++)
#pragma unroll
                for (int e = 0; e < 4; e++) sacc[nt][e] = 0.f;

#pragma unroll
            for (int kt = 0; kt < 8; kt++) {
#pragma unroll
                for (int nt = 0; nt < 8; nt++) {
                    uint32_t bb[2];
                    const float* krow = Ksm + (size_t)(nt * 8 + tr) * PADK + kt * 8 + tc;
                    bb[0] = f2tf32(krow[0]);
                    bb[1] = f2tf32(krow[4]);
                    mma_tf32(sacc[nt], qfrag[kt], bb);
                }
            }

            // ---- online softmax ----
            const bool need_mask = (kb + TKA - 1) > wrow;
            float mx0 = -1e30f, mx1 = -1e30f;
#pragma unroll
            for (int nt = 0; nt < 8; nt++) {
                int c0 = kb + nt * 8 + 2 * tc;
                float z0 = sacc[nt][0] * CSC;
                float z1 = sacc[nt][1] * CSC;
                float z2 = sacc[nt][2] * CSC;
                float z3 = sacc[nt][3] * CSC;
                if (need_mask) {
                    if (c0     > gr0) z0 = -1e30f;
                    if (c0 + 1 > gr0) z1 = -1e30f;
                    if (c0     > gr0 + 8) z2 = -1e30f;
                    if (c0 + 1 > gr0 + 8) z3 = -1e30f;
                }
                sacc[nt][0] = z0; sacc[nt][1] = z1;
                sacc[nt][2] = z2; sacc[nt][3] = z3;
                mx0 = fmaxf(mx0, fmaxf(z0, z1));
                mx1 = fmaxf(mx1, fmaxf(z2, z3));
            }
            mx0 = fmaxf(mx0, __shfl_xor_sync(0xffffffffu, mx0, 1));
            mx0 = fmaxf(mx0, __shfl_xor_sync(0xffffffffu, mx0, 2));
            mx1 = fmaxf(mx1, __shfl_xor_sync(0xffffffffu, mx1, 1));
            mx1 = fmaxf(mx1, __shfl_xor_sync(0xffffffffu, mx1, 2));

            float m0n = fmaxf(m0, mx0);
            float m1n = fmaxf(m1, mx1);
            float f0 = exp2f(m0 - m0n);
            float f1 = exp2f(m1 - m1n);

            // exp -> P fragments kept in registers (tf32 bits)
            uint32_t pcu[8][4];
            float sum0 = 0.f, sum1 = 0.f;
#pragma unroll
            for (int nt = 0; nt < 8; nt++) {
                float p00 = exp2f(sacc[nt][0] - m0n);
                float p01 = exp2f(sacc[nt][1] - m0n);
                float p10 = exp2f(sacc[nt][2] - m1n);
                float p11 = exp2f(sacc[nt][3] - m1n);
                sum0 += p00 + p01;
                sum1 += p10 + p11;
                pcu[nt][0] = f2tf32(p00);
                pcu[nt][1] = f2tf32(p01);
                pcu[nt][2] = f2tf32(p10);
                pcu[nt][3] = f2tf32(p11);
            }
            sum0 += __shfl_xor_sync(0xffffffffu, sum0, 1);
            sum0 += __shfl_xor_sync(0xffffffffu, sum0, 2);
            sum1 += __shfl_xor_sync(0xffffffffu, sum1, 1);
            sum1 += __shfl_xor_sync(0xffffffffu, sum1, 2);

            l0 = l0 * f0 + sum0;
            l1 = l1 * f1 + sum1;
            m0 = m0n; m1 = m1n;
#pragma unroll
            for (int nt = 0; nt < 8; nt++) {
                oacc[nt][0] *= f0; oacc[nt][1] *= f0;
                oacc[nt][2] *= f1; oacc[nt][3] *= f1;
            }

            // ---- O += P @ V : A-fragment built from sacc via intra-quad shfl ----
            const int basel = lane & ~3;
            const int sl  = basel + (tc >> 1);
            const int sl2 = sl + 2;
            const bool odd = (tc & 1);
#pragma unroll
            for (int kt = 0; kt < 8; kt++) {
                uint32_t x0 = __shfl_sync(0xffffffffu, pcu[kt][0], sl);
                uint32_t x1 = __shfl_sync(0xffffffffu, pcu[kt][1], sl);
                uint32_t y0 = __shfl_sync(0xffffffffu, pcu[kt][0], sl2);
                uint32_t y1 = __shfl_sync(0xffffffffu, pcu[kt][1], sl2);
                uint32_t z0 = __shfl_sync(0xffffffffu, pcu[kt][2], sl);
                uint32_t z1 = __shfl_sync(0xffffffffu, pcu[kt][3], sl);
                uint32_t w0 = __shfl_sync(0xffffffffu, pcu[kt][2], sl2);
                uint32_t w1 = __shfl_sync(0xffffffffu, pcu[kt][3], sl2);
                uint32_t pa[4];
                pa[0] = odd ? x1 : x0;   // P[tr   ][kt*8 + tc    ]
                pa[1] = odd ? z1 : z0;   // P[tr+8 ][kt*8 + tc    ]
                pa[2] = odd ? y1 : y0;   // P[tr   ][kt*8 + tc + 4]
                pa[3] = odd ? w1 : w0;   // P[tr+8 ][kt*8 + tc + 4]
#pragma unroll
                for (int nt = 0; nt < 8; nt++) {
                    uint32_t vb[2];
                    const float* vrow = Vsm + (size_t)(kt * 8 + tc) * PADK + nt * 8 + tr;
                    vb[0] = f2tf32(vrow[0]);
                    vb[1] = f2tf32(vrow[4 * PADK]);
                    mma_tf32(oacc[nt], pa, vb);
                }
            }
        }
        __syncthreads();   // all compute on this stage done before it is reloaded
    }

    // Epilogue: normalize, split to bf16 hi/lo, write (fused split)
    float il0 = 1.0f / l0;
    float il1 = 1.0f / l1;
    size_t base0 = (size_t)(rowbase + gr0) * EMBED + h * HDIM + 2 * tc;
    size_t base1 = base0 + 8 * EMBED;
#pragma unroll
    for (int nt = 0; nt < 8; nt++) {
        float o00 = oacc[nt][0] * il0, o01 = oacc[nt][1] * il0;
        float o10 = oacc[nt][2] * il1, o11 = oacc[nt][3] * il1;
        __nv_bfloat16 h00 = __float2bfloat16(o00), h01 = __float2bfloat16(o01);
        __nv_bfloat16 h10 = __float2bfloat16(o10), h11 = __float2bfloat16(o11);
        *reinterpret_cast<__nv_bfloat162*>(&g_a_hi[base0 + nt * 8]) = __nv_bfloat162(h00, h01);
        *reinterpret_cast<__nv_bfloat162*>(&g_a_hi[base1 + nt * 8]) = __nv_bfloat162(h10, h11);
        *reinterpret_cast<__nv_bfloat162*>(&g_a_lo[base0 + nt * 8]) =
            __nv_bfloat162(__float2bfloat16(o00 - __bfloat162float(h00)),
                           __float2bfloat16(o01 - __bfloat162float(h01)));
        *reinterpret_cast<__nv_bfloat162*>(&g_a_lo[base1 + nt * 8]) =
            __nv_bfloat162(__float2bfloat16(o10 - __bfloat162float(h10)),
                           __float2bfloat16(o11 - __bfloat162float(h11)));
    }
}

// ---------------------------------------------------------------------------
// Launch
// ---------------------------------------------------------------------------
extern "C" void kernel_launch(void* const* d_in, const int* in_sizes, int n_in,
                              void* d_out, int out_size)
{
    const float* x     = (const float*)d_in[0];
    const float* qkv_w = (const float*)d_in[1];
    const float* out_w = (const float*)d_in[2];
    float* out = (float*)d_out;

    static bool attr_done = false;
    if (!attr_done) {
        cudaFuncSetAttribute(gemm3bf16_mma, cudaFuncAttributeMaxDynamicSharedMemorySize, GEMM_SMEM);
        cudaFuncSetAttribute(attn_tc_kernel, cudaFuncAttributeMaxDynamicSharedMemorySize, ATT_SMEM);
        attr_done = true;
    }

    __nv_bfloat16 *xh, *xl, *w1h, *w1l, *w2h, *w2l, *ah, *al;
    float *qkv;
    cudaGetSymbolAddress((void**)&xh,  g_x_hi);
    cudaGetSymbolAddress((void**)&xl,  g_x_lo);
    cudaGetSymbolAddress((void**)&w1h, g_w1_hi);
    cudaGetSymbolAddress((void**)&w1l, g_w1_lo);
    cudaGetSymbolAddress((void**)&w2h, g_w2_hi);
    cudaGetSymbolAddress((void**)&w2l, g_w2_lo);
    cudaGetSymbolAddress((void**)&ah,  g_a_hi);
    cudaGetSymbolAddress((void**)&al,  g_a_lo);
    cudaGetSymbolAddress((void**)&qkv, g_qkv);

    // 0) split inputs into bf16 hi/lo (float4 vectorized)
    {
        int n1 = MROWS * EMBED / 4;
        split4_kernel<<<(n1 + 255) / 256, 256>>>(x, xh, xl, n1);
        int n2 = D3 * EMBED / 4;
        split4_kernel<<<(n2 + 255) / 256, 256>>>(qkv_w, w1h, w1l, n2);
        int n3 = EMBED * EMBED / 4;
        split4_kernel<<<(n3 + 255) / 256, 256>>>(out_w, w2h, w2l, n3);
    }

    // 1) QKV projection
    {
        dim3 grid(D3 / 128, MROWS / 128);
        gemm3bf16_mma<<<grid, 128, GEMM_SMEM>>>(xh, xl, w1h, w1l, qkv, MROWS, D3, EMBED);
    }

    // 2) Causal flash attention (tf32, register-resident P, fused split)
    {
        dim3 grid(SEQ / TQA, NHEADS, BATCH);
        attn_tc_kernel<<<grid, 256, ATT_SMEM>>>();
    }

    // 3) out projection (reads fused-split attention output)
    {
        dim3 grid(EMBED / 128, MROWS / 128);
        gemm3bf16_mma<<<grid, 128, GEMM_SMEM>>>(ah, al, w2h, w2l, out, MROWS, EMBED, EMBED);
    }
}

// round 9
// speedup vs baseline: 1.3212x; 1.1064x over previous
#include <cuda_runtime.h>
#include <cuda_bf16.h>
#include <cstdint>

// Problem constants
#define BATCH   2
#define SEQ     2048
#define EMBED   1024
#define NHEADS  16
#define HDIM    64
#define D3      (3 * EMBED)          // 3072
#define MROWS   (BATCH * SEQ)        // 4096

// ---------------------------------------------------------------------------
// Scratch (static device globals: allocation-free per harness rules)
// ---------------------------------------------------------------------------
__device__ float g_qkv [(size_t)MROWS * D3];      // (4096, 3072)
__device__ float g_attn[(size_t)MROWS * EMBED];   // (4096, 1024)

// ---------------------------------------------------------------------------
// PTX helpers (base sm_103-legal: mma.sync / cp.async only)
// ---------------------------------------------------------------------------
__device__ __forceinline__ uint32_t smem_u32(const void* p) {
    uint32_t a;
    asm("{ .reg .u64 t; cvta.to.shared.u64 t, %1; cvt.u32.u64 %0, t; }" : "=r"(a) : "l"(p));
    return a;
}
__device__ __forceinline__ void cp_async16(uint32_t dst, const void* src) {
    asm volatile("cp.async.cg.shared.global [%0], [%1], 16;" :: "r"(dst), "l"(src));
}
__device__ __forceinline__ void cp_commit() {
    asm volatile("cp.async.commit_group;" ::: "memory");
}
template <int N>
__device__ __forceinline__ void cp_wait() {
    asm volatile("cp.async.wait_group %0;" :: "n"(N) : "memory");
}
__device__ __forceinline__ uint32_t f2tf32(float f) {
    uint32_t r;
    asm("cvt.rna.tf32.f32 %0, %1;" : "=r"(r) : "f"(f));
    return r;
}
__device__ __forceinline__ void mma_tf32(float* c, const uint32_t* a, const uint32_t* b) {
    asm volatile(
        "mma.sync.aligned.m16n8k8.row.col.f32.tf32.tf32.f32 "
        "{%0,%1,%2,%3}, {%4,%5,%6,%7}, {%8,%9}, {%0,%1,%2,%3};"
        : "+f"(c[0]), "+f"(c[1]), "+f"(c[2]), "+f"(c[3])
        : "r"(a[0]), "r"(a[1]), "r"(a[2]), "r"(a[3]), "r"(b[0]), "r"(b[1]));
}

// ---------------------------------------------------------------------------
// TF32 GEMM: C[M,N] = A[M,K] * B[N,K]^T  (A, B raw fp32, K-major)
// BM=BN=128, BK=32, 128 threads (4 warps), warp tile 64x64,
// 2-stage cp.async pipeline, 2 CTAs/SM.
// smem tiles: 128 rows x 36 floats (32 payload + 4 pad) -> conflict-free LDS
//   bank(a0 lane) = (36*tr + tc) mod 32 = (4*tr + tc) mod 32, all distinct.
// ---------------------------------------------------------------------------
#define GROWF    36                          // floats per smem row (stride)
#define GROWB    (GROWF * 4)                 // 144 bytes
#define GTILE_B  (128 * GROWB)               // 18432
#define GSTAGE_B (2 * GTILE_B)               // 36864 (A + B)
#define GEMM_SMEM (2 * GSTAGE_B)             // 73728

__device__ __forceinline__ void load_stage_tf32(uint32_t sbase,
                                                const float* __restrict__ A,
                                                const float* __restrict__ B,
                                                int bm, int bn, int K, int k0, int tid)
{
#pragma unroll
    for (int rep = 0; rep < 16; rep++) {
        const int t = rep >> 3;              // 0 = A, 1 = B (compile-time)
        int e   = tid + (rep & 7) * 128;     // 0..1023
        int row = e >> 3;                    // 0..127
        int ch  = e & 7;                     // 16B chunk (4 floats)
        const float* src = (t == 0)
            ? A + (size_t)(bm + row) * K + k0 + ch * 4
            : B + (size_t)(bn + row) * K + k0 + ch * 4;
        cp_async16(sbase + (uint32_t)t * GTILE_B + (uint32_t)(row * GROWB + ch * 16), src);
    }
}

__global__ __launch_bounds__(128, 2) void gemm_tf32(
    const float* __restrict__ A, const float* __restrict__ B,
    float* __restrict__ C, int M, int N, int K)
{
    extern __shared__ __align__(16) float dynf[];
    const uint32_t sb = smem_u32(dynf);

    const int tid  = threadIdx.x;
    const int lane = tid & 31;
    const int wid  = tid >> 5;
    const int wm   = wid >> 1;            // 0..1 (M, 64 rows)
    const int wn   = wid & 1;             // 0..1 (N, 64 cols)
    const int tr   = lane >> 2;           // 0..7
    const int tc   = lane & 3;            // 0..3
    const int bm   = blockIdx.y * 128;
    const int bn   = blockIdx.x * 128;

    float acc[4][8][4];
#pragma unroll
    for (int i = 0; i < 4; i++)
#pragma unroll
        for (int j = 0; j < 8; j++)
#pragma unroll
            for (int k = 0; k < 4; k++) acc[i][j][k] = 0.f;

    const int NIT = K / 32;

    load_stage_tf32(sb, A, B, bm, bn, K, 0, tid);
    cp_commit();

    for (int it = 0; it < NIT; it++) {
        if (it + 1 < NIT) {
            load_stage_tf32(sb + (uint32_t)((it + 1) & 1) * GSTAGE_B,
                            A, B, bm, bn, K, (it + 1) * 32, tid);
            cp_commit();
            cp_wait<1>();
        } else {
            cp_wait<0>();
        }
        __syncthreads();

        const float* As = dynf + (size_t)(it & 1) * (GSTAGE_B / 4);
        const float* Bs = As + GTILE_B / 4;

#pragma unroll
        for (int kt = 0; kt < 4; kt++) {
            const int k0 = kt * 8;

            uint32_t afr[4][4];
#pragma unroll
            for (int mt = 0; mt < 4; mt++) {
                const float* ap = As + (size_t)(wm * 64 + mt * 16 + tr) * GROWF + k0 + tc;
                afr[mt][0] = f2tf32(ap[0]);
                afr[mt][1] = f2tf32(ap[8 * GROWF]);
                afr[mt][2] = f2tf32(ap[4]);
                afr[mt][3] = f2tf32(ap[8 * GROWF + 4]);
            }

#pragma unroll
            for (int nt = 0; nt < 8; nt++) {
                const float* bp = Bs + (size_t)(wn * 64 + nt * 8 + tr) * GROWF + k0 + tc;
                uint32_t bb[2];
                bb[0] = f2tf32(bp[0]);
                bb[1] = f2tf32(bp[4]);
#pragma unroll
                for (int mt = 0; mt < 4; mt++)
                    mma_tf32(acc[mt][nt], afr[mt], bb);
            }
        }
        __syncthreads();
    }

#pragma unroll
    for (int mt = 0; mt < 4; mt++) {
        int row = bm + wm * 64 + mt * 16 + tr;
#pragma unroll
        for (int nt = 0; nt < 8; nt++) {
            int col = bn + wn * 64 + nt * 8 + tc * 2;
            *reinterpret_cast<float2*>(&C[(size_t)row * N + col]) =
                make_float2(acc[mt][nt][0], acc[mt][nt][1]);
            *reinterpret_cast<float2*>(&C[(size_t)(row + 8) * N + col]) =
                make_float2(acc[mt][nt][2], acc[mt][nt][3]);
        }
    }
}

// ---------------------------------------------------------------------------
// TF32 tensor-core causal flash attention (R8 v3):
//  - Q fragments in registers, K/V double-buffered cp.async,
//    register-resident P via intra-quad shfl, fp32 output to g_attn.
// ---------------------------------------------------------------------------
#define TQA   128
#define TKA   64
#define PADK  68
#define KVT_F  (64 * PADK)
#define STG_F  (2 * KVT_F)
#define ATT_SMEM (2 * STG_F * 4)           // 69632 bytes

__global__ __launch_bounds__(256, 1) void attn_tc_kernel()
{
    extern __shared__ float smf[];

    const int tid  = threadIdx.x;
    const int lane = tid & 31;
    const int w    = tid >> 5;
    const int tr   = lane >> 2;
    const int tc   = lane & 3;

    const int qi = (int)gridDim.x - 1 - (int)blockIdx.x;
    const int h  = blockIdx.y;
    const int b  = blockIdx.z;
    const int qb = qi * TQA;
    const size_t rowbase = (size_t)b * SEQ;

    const float* qptr = g_qkv + rowbase * D3 + h * HDIM;
    const float* kptr = qptr + EMBED;
    const float* vptr = qptr + 2 * EMBED;

    // Stage Q tile through stage-0 smem, then to registers.
    for (int i = tid; i < 128 * 16; i += 256) {
        int r = i >> 4, c4 = (i & 15) * 4;
        float4 v = *reinterpret_cast<const float4*>(qptr + (size_t)(qb + r) * D3 + c4);
        float* dst = smf + r * PADK + c4;
        dst[0] = v.x; dst[1] = v.y; dst[2] = v.z; dst[3] = v.w;
    }
    __syncthreads();

    uint32_t qfrag[8][4];
    {
        const float* qrow = smf + (size_t)(w * 16 + tr) * PADK + tc;
#pragma unroll
        for (int kt = 0; kt < 8; kt++) {
            qfrag[kt][0] = f2tf32(qrow[kt * 8]);
            qfrag[kt][1] = f2tf32(qrow[8 * PADK + kt * 8]);
            qfrag[kt][2] = f2tf32(qrow[kt * 8 + 4]);
            qfrag[kt][3] = f2tf32(qrow[8 * PADK + kt * 8 + 4]);
        }
    }
    __syncthreads();

    const uint32_t s0 = smem_u32(smf);

    float oacc[8][4];
#pragma unroll
    for (int nt = 0; nt < 8; nt++)
#pragma unroll
        for (int e = 0; e < 4; e++) oacc[nt][e] = 0.f;

    float m0 = -1e30f, m1 = -1e30f, l0 = 0.f, l1 = 0.f;

    const float CSC = 0.18033688f;   // (1/sqrt(64)) * log2(e)
    const int wrow  = qb + w * 16;
    const int gr0   = wrow + tr;
    const int jmax  = (qb + TQA - 1) / TKA;

#pragma unroll
    for (int rep = 0; rep < 4; rep++) {
        int i = tid + rep * 256;
        int r = i >> 4, c4 = (i & 15) * 4;
        uint32_t soff = (uint32_t)(r * PADK + c4) * 4;
        cp_async16(s0 + soff,             kptr + (size_t)r * D3 + c4);
        cp_async16(s0 + KVT_F * 4 + soff, vptr + (size_t)r * D3 + c4);
    }
    cp_commit();

    for (int j = 0; j <= jmax; j++) {
        const int kb = j * TKA;

        if (j < jmax) {
            const int kb1 = (j + 1) * TKA;
            const uint32_t sst = s0 + (uint32_t)(((j + 1) & 1) * STG_F) * 4;
#pragma unroll
            for (int rep = 0; rep < 4; rep++) {
                int i = tid + rep * 256;
                int r = i >> 4, c4 = (i & 15) * 4;
                uint32_t soff = (uint32_t)(r * PADK + c4) * 4;
                cp_async16(sst + soff,             kptr + (size_t)(kb1 + r) * D3 + c4);
                cp_async16(sst + KVT_F * 4 + soff, vptr + (size_t)(kb1 + r) * D3 + c4);
            }
            cp_commit();
            cp_wait<1>();
        } else {
            cp_wait<0>();
        }
        __syncthreads();

        const float* Ksm = smf + (j & 1) * STG_F;
        const float* Vsm = Ksm + KVT_F;

        if (kb <= wrow + 15) {
            float sacc[8][4];
#pragma unroll
            for (int nt = 0; nt < 8; nt++)
#pragma unroll
                for (int e = 0; e < 4; e++) sacc[nt][e] = 0.f;

#pragma unroll
            for (int kt = 0; kt < 8; kt++) {
#pragma unroll
                for (int nt = 0; nt < 8; nt++) {
                    uint32_t bb[2];
                    const float* krow = Ksm + (size_t)(nt * 8 + tr) * PADK + kt * 8 + tc;
                    bb[0] = f2tf32(krow[0]);
                    bb[1] = f2tf32(krow[4]);
                    mma_tf32(sacc[nt], qfrag[kt], bb);
                }
            }

            const bool need_mask = (kb + TKA - 1) > wrow;
            float mx0 = -1e30f, mx1 = -1e30f;
#pragma unroll
            for (int nt = 0; nt < 8; nt++) {
                int c0 = kb + nt * 8 + 2 * tc;
                float z0 = sacc[nt][0] * CSC;
                float z1 = sacc[nt][1] * CSC;
                float z2 = sacc[nt][2] * CSC;
                float z3 = sacc[nt][3] * CSC;
                if (need_mask) {
                    if (c0     > gr0) z0 = -1e30f;
                    if (c0 + 1 > gr0) z1 = -1e30f;
                    if (c0     > gr0 + 8) z2 = -1e30f;
                    if (c0 + 1 > gr0 + 8) z3 = -1e30f;
                }
                sacc[nt][0] = z0; sacc[nt][1] = z1;
                sacc[nt][2] = z2; sacc[nt][3] = z3;
                mx0 = fmaxf(mx0, fmaxf(z0, z1));
                mx1 = fmaxf(mx1, fmaxf(z2, z3));
            }
            mx0 = fmaxf(mx0, __shfl_xor_sync(0xffffffffu, mx0, 1));
            mx0 = fmaxf(mx0, __shfl_xor_sync(0xffffffffu, mx0, 2));
            mx1 = fmaxf(mx1, __shfl_xor_sync(0xffffffffu, mx1, 1));
            mx1 = fmaxf(mx1, __shfl_xor_sync(0xffffffffu, mx1, 2));

            float m0n = fmaxf(m0, mx0);
            float m1n = fmaxf(m1, mx1);
            float f0 = exp2f(m0 - m0n);
            float f1 = exp2f(m1 - m1n);

            uint32_t pcu[8][4];
            float sum0 = 0.f, sum1 = 0.f;
#pragma unroll
            for (int nt = 0; nt < 8; nt++) {
                float p00 = exp2f(sacc[nt][0] - m0n);
                float p01 = exp2f(sacc[nt][1] - m0n);
                float p10 = exp2f(sacc[nt][2] - m1n);
                float p11 = exp2f(sacc[nt][3] - m1n);
                sum0 += p00 + p01;
                sum1 += p10 + p11;
                pcu[nt][0] = f2tf32(p00);
                pcu[nt][1] = f2tf32(p01);
                pcu[nt][2] = f2tf32(p10);
                pcu[nt][3] = f2tf32(p11);
            }
            sum0 += __shfl_xor_sync(0xffffffffu, sum0, 1);
            sum0 += __shfl_xor_sync(0xffffffffu, sum0, 2);
            sum1 += __shfl_xor_sync(0xffffffffu, sum1, 1);
            sum1 += __shfl_xor_sync(0xffffffffu, sum1, 2);

            l0 = l0 * f0 + sum0;
            l1 = l1 * f1 + sum1;
            m0 = m0n; m1 = m1n;
#pragma unroll
            for (int nt = 0; nt < 8; nt++) {
                oacc[nt][0] *= f0; oacc[nt][1] *= f0;
                oacc[nt][2] *= f1; oacc[nt][3] *= f1;
            }

            const int basel = lane & ~3;
            const int sl  = basel + (tc >> 1);
            const int sl2 = sl + 2;
            const bool odd = (tc & 1);
#pragma unroll
            for (int kt = 0; kt < 8; kt++) {
                uint32_t x0 = __shfl_sync(0xffffffffu, pcu[kt][0], sl);
                uint32_t x1 = __shfl_sync(0xffffffffu, pcu[kt][1], sl);
                uint32_t y0 = __shfl_sync(0xffffffffu, pcu[kt][0], sl2);
                uint32_t y1 = __shfl_sync(0xffffffffu, pcu[kt][1], sl2);
                uint32_t z0 = __shfl_sync(0xffffffffu, pcu[kt][2], sl);
                uint32_t z1 = __shfl_sync(0xffffffffu, pcu[kt][3], sl);
                uint32_t w0 = __shfl_sync(0xffffffffu, pcu[kt][2], sl2);
                uint32_t w1 = __shfl_sync(0xffffffffu, pcu[kt][3], sl2);
                uint32_t pa[4];
                pa[0] = odd ? x1 : x0;
                pa[1] = odd ? z1 : z0;
                pa[2] = odd ? y1 : y0;
                pa[3] = odd ? w1 : w0;
#pragma unroll
                for (int nt = 0; nt < 8; nt++) {
                    uint32_t vb[2];
                    const float* vrow = Vsm + (size_t)(kt * 8 + tc) * PADK + nt * 8 + tr;
                    vb[0] = f2tf32(vrow[0]);
                    vb[1] = f2tf32(vrow[4 * PADK]);
                    mma_tf32(oacc[nt], pa, vb);
                }
            }
        }
        __syncthreads();
    }

    // Epilogue: normalize, write fp32 to g_attn
    float il0 = 1.0f / l0;
    float il1 = 1.0f / l1;
    float* obase = g_attn + (size_t)(rowbase + gr0) * EMBED + h * HDIM + 2 * tc;
#pragma unroll
    for (int nt = 0; nt < 8; nt++) {
        *reinterpret_cast<float2*>(obase + nt * 8) =
            make_float2(oacc[nt][0] * il0, oacc[nt][1] * il0);
        *reinterpret_cast<float2*>(obase + 8 * EMBED + nt * 8) =
            make_float2(oacc[nt][2] * il1, oacc[nt][3] * il1);
    }
}

// ---------------------------------------------------------------------------
// Launch
// ---------------------------------------------------------------------------
extern "C" void kernel_launch(void* const* d_in, const int* in_sizes, int n_in,
                              void* d_out, int out_size)
{
    const float* x     = (const float*)d_in[0];
    const float* qkv_w = (const float*)d_in[1];
    const float* out_w = (const float*)d_in[2];
    float* out = (float*)d_out;

    static bool attr_done = false;
    if (!attr_done) {
        cudaFuncSetAttribute(gemm_tf32, cudaFuncAttributeMaxDynamicSharedMemorySize, GEMM_SMEM);
        cudaFuncSetAttribute(attn_tc_kernel, cudaFuncAttributeMaxDynamicSharedMemorySize, ATT_SMEM);
        attr_done = true;
    }

    float *qkv, *attn;
    cudaGetSymbolAddress((void**)&qkv,  g_qkv);
    cudaGetSymbolAddress((void**)&attn, g_attn);

    // 1) QKV projection (tf32): g_qkv = x @ qkv_w^T
    {
        dim3 grid(D3 / 128, MROWS / 128);
        gemm_tf32<<<grid, 128, GEMM_SMEM>>>(x, qkv_w, qkv, MROWS, D3, EMBED);
    }

    // 2) Causal flash attention (tf32, register-resident P)
    {
        dim3 grid(SEQ / TQA, NHEADS, BATCH);
        attn_tc_kernel<<<grid, 256, ATT_SMEM>>>();
    }

    // 3) Output projection (tf32): out = g_attn @ out_w^T
    {
        dim3 grid(EMBED / 128, MROWS / 128);
        gemm_tf32<<<grid, 128, GEMM_SMEM>>>(attn, out_w, out, MROWS, EMBED, EMBED);
    }
}

// round 10
// speedup vs baseline: 1.3918x; 1.0535x over previous
#include <cuda_runtime.h>
#include <cuda_bf16.h>
#include <cstdint>

// Problem constants
#define BATCH   2
#define SEQ     2048
#define EMBED   1024
#define NHEADS  16
#define HDIM    64
#define D3      (3 * EMBED)          // 3072
#define MROWS   (BATCH * SEQ)        // 4096

// ---------------------------------------------------------------------------
// Scratch (static device globals: allocation-free per harness rules)
// ---------------------------------------------------------------------------
__device__ float g_qkv [(size_t)MROWS * D3];      // (4096, 3072), tf32-rounded
__device__ float g_attn[(size_t)MROWS * EMBED];   // (4096, 1024), tf32-rounded

__device__ __align__(16) float g_x_t [(size_t)MROWS * EMBED];   // tf32-rounded x
__device__ __align__(16) float g_w1_t[(size_t)D3 * EMBED];      // tf32-rounded qkv_w
__device__ __align__(16) float g_w2_t[(size_t)EMBED * EMBED];   // tf32-rounded out_w

// ---------------------------------------------------------------------------
// PTX helpers (base sm_103-legal: mma.sync / cp.async only)
// ---------------------------------------------------------------------------
__device__ __forceinline__ uint32_t smem_u32(const void* p) {
    uint32_t a;
    asm("{ .reg .u64 t; cvta.to.shared.u64 t, %1; cvt.u32.u64 %0, t; }" : "=r"(a) : "l"(p));
    return a;
}
__device__ __forceinline__ void cp_async16(uint32_t dst, const void* src) {
    asm volatile("cp.async.cg.shared.global [%0], [%1], 16;" :: "r"(dst), "l"(src));
}
__device__ __forceinline__ void cp_commit() {
    asm volatile("cp.async.commit_group;" ::: "memory");
}
template <int N>
__device__ __forceinline__ void cp_wait() {
    asm volatile("cp.async.wait_group %0;" :: "n"(N) : "memory");
}
__device__ __forceinline__ uint32_t f2tf32(float f) {
    uint32_t r;
    asm("cvt.rna.tf32.f32 %0, %1;" : "=r"(r) : "f"(f));
    return r;
}
__device__ __forceinline__ float roundtf(float f) {
    return __uint_as_float(f2tf32(f));
}
__device__ __forceinline__ void mma_tf32(float* c, const uint32_t* a, const uint32_t* b) {
    asm volatile(
        "mma.sync.aligned.m16n8k8.row.col.f32.tf32.tf32.f32 "
        "{%0,%1,%2,%3}, {%4,%5,%6,%7}, {%8,%9}, {%0,%1,%2,%3};"
        : "+f"(c[0]), "+f"(c[1]), "+f"(c[2]), "+f"(c[3])
        : "r"(a[0]), "r"(a[1]), "r"(a[2]), "r"(a[3]), "r"(b[0]), "r"(b[1]));
}

// ---------------------------------------------------------------------------
// fp32 -> tf32-rounded fp32 copy (float4)
// ---------------------------------------------------------------------------
__global__ void round_tf32_kernel(const float* __restrict__ src,
                                  float* __restrict__ dst, int n4)
{
    int i = blockIdx.x * blockDim.x + threadIdx.x;
    if (i >= n4) return;
    float4 v = reinterpret_cast<const float4*>(src)[i];
    float4 o;
    o.x = roundtf(v.x); o.y = roundtf(v.y); o.z = roundtf(v.z); o.w = roundtf(v.w);
    reinterpret_cast<float4*>(dst)[i] = o;
}

// ---------------------------------------------------------------------------
// TF32 GEMM: C[M,N] = A[M,K] * B[N,K]^T  (A, B pre-rounded tf32 bits in fp32)
// BM=BN=128, BK=32, 128 threads (4 warps), warp tile 64x64,
// 2-stage cp.async pipeline, 2 CTAs/SM. No CVT in inner loop.
// ROUND_C: round output to tf32 (for tensors consumed by later tf32 MMAs).
// ---------------------------------------------------------------------------
#define GROWF    36
#define GROWB    (GROWF * 4)                 // 144 bytes
#define GTILE_B  (128 * GROWB)               // 18432
#define GSTAGE_B (2 * GTILE_B)               // 36864
#define GEMM_SMEM (2 * GSTAGE_B)             // 73728

__device__ __forceinline__ void load_stage_tf32(uint32_t sbase,
                                                const float* __restrict__ A,
                                                const float* __restrict__ B,
                                                int bm, int bn, int K, int k0, int tid)
{
#pragma unroll
    for (int rep = 0; rep < 16; rep++) {
        const int t = rep >> 3;
        int e   = tid + (rep & 7) * 128;
        int row = e >> 3;
        int ch  = e & 7;
        const float* src = (t == 0)
            ? A + (size_t)(bm + row) * K + k0 + ch * 4
            : B + (size_t)(bn + row) * K + k0 + ch * 4;
        cp_async16(sbase + (uint32_t)t * GTILE_B + (uint32_t)(row * GROWB + ch * 16), src);
    }
}

template <bool ROUND_C>
__global__ __launch_bounds__(128, 2) void gemm_tf32(
    const float* __restrict__ A, const float* __restrict__ B,
    float* __restrict__ C, int M, int N, int K)
{
    extern __shared__ __align__(16) float dynf[];
    const uint32_t sb = smem_u32(dynf);

    const int tid  = threadIdx.x;
    const int lane = tid & 31;
    const int wid  = tid >> 5;
    const int wm   = wid >> 1;
    const int wn   = wid & 1;
    const int tr   = lane >> 2;
    const int tc   = lane & 3;
    const int bm   = blockIdx.y * 128;
    const int bn   = blockIdx.x * 128;

    float acc[4][8][4];
#pragma unroll
    for (int i = 0; i < 4; i++)
#pragma unroll
        for (int j = 0; j < 8; j++)
#pragma unroll
            for (int k = 0; k < 4; k++) acc[i][j][k] = 0.f;

    const int NIT = K / 32;

    load_stage_tf32(sb, A, B, bm, bn, K, 0, tid);
    cp_commit();

    for (int it = 0; it < NIT; it++) {
        if (it + 1 < NIT) {
            load_stage_tf32(sb + (uint32_t)((it + 1) & 1) * GSTAGE_B,
                            A, B, bm, bn, K, (it + 1) * 32, tid);
            cp_commit();
            cp_wait<1>();
        } else {
            cp_wait<0>();
        }
        __syncthreads();

        const float* As = dynf + (size_t)(it & 1) * (GSTAGE_B / 4);
        const float* Bs = As + GTILE_B / 4;

#pragma unroll
        for (int kt = 0; kt < 4; kt++) {
            const int k0 = kt * 8;

            uint32_t afr[4][4];
#pragma unroll
            for (int mt = 0; mt < 4; mt++) {
                const float* ap = As + (size_t)(wm * 64 + mt * 16 + tr) * GROWF + k0 + tc;
                afr[mt][0] = __float_as_uint(ap[0]);
                afr[mt][1] = __float_as_uint(ap[8 * GROWF]);
                afr[mt][2] = __float_as_uint(ap[4]);
                afr[mt][3] = __float_as_uint(ap[8 * GROWF + 4]);
            }

#pragma unroll
            for (int nt = 0; nt < 8; nt++) {
                const float* bp = Bs + (size_t)(wn * 64 + nt * 8 + tr) * GROWF + k0 + tc;
                uint32_t bb[2];
                bb[0] = __float_as_uint(bp[0]);
                bb[1] = __float_as_uint(bp[4]);
#pragma unroll
                for (int mt = 0; mt < 4; mt++)
                    mma_tf32(acc[mt][nt], afr[mt], bb);
            }
        }
        __syncthreads();
    }

#pragma unroll
    for (int mt = 0; mt < 4; mt++) {
        int row = bm + wm * 64 + mt * 16 + tr;
#pragma unroll
        for (int nt = 0; nt < 8; nt++) {
            int col = bn + wn * 64 + nt * 8 + tc * 2;
            float c0 = acc[mt][nt][0], c1 = acc[mt][nt][1];
            float c2 = acc[mt][nt][2], c3 = acc[mt][nt][3];
            if (ROUND_C) {
                c0 = roundtf(c0); c1 = roundtf(c1);
                c2 = roundtf(c2); c3 = roundtf(c3);
            }
            *reinterpret_cast<float2*>(&C[(size_t)row * N + col]) = make_float2(c0, c1);
            *reinterpret_cast<float2*>(&C[(size_t)(row + 8) * N + col]) = make_float2(c2, c3);
        }
    }
}

// ---------------------------------------------------------------------------
// TF32 tensor-core causal flash attention:
//  - inputs (g_qkv) pre-rounded to tf32 -> no CVT on Q/K/V fragments
//  - Q fragments in registers, K/V double-buffered cp.async,
//    register-resident P via intra-quad shfl
//  - epilogue rounds output to tf32 for the out-projection GEMM
// ---------------------------------------------------------------------------
#define TQA   128
#define TKA   64
#define PADK  68
#define KVT_F  (64 * PADK)
#define STG_F  (2 * KVT_F)
#define ATT_SMEM (2 * STG_F * 4)           // 69632 bytes

__global__ __launch_bounds__(256, 1) void attn_tc_kernel()
{
    extern __shared__ float smf[];

    const int tid  = threadIdx.x;
    const int lane = tid & 31;
    const int w    = tid >> 5;
    const int tr   = lane >> 2;
    const int tc   = lane & 3;

    const int qi = (int)gridDim.x - 1 - (int)blockIdx.x;
    const int h  = blockIdx.y;
    const int b  = blockIdx.z;
    const int qb = qi * TQA;
    const size_t rowbase = (size_t)b * SEQ;

    const float* qptr = g_qkv + rowbase * D3 + h * HDIM;
    const float* kptr = qptr + EMBED;
    const float* vptr = qptr + 2 * EMBED;

    // Stage Q tile through stage-0 smem, then to registers (already tf32 bits).
    for (int i = tid; i < 128 * 16; i += 256) {
        int r = i >> 4, c4 = (i & 15) * 4;
        float4 v = *reinterpret_cast<const float4*>(qptr + (size_t)(qb + r) * D3 + c4);
        float* dst = smf + r * PADK + c4;
        dst[0] = v.x; dst[1] = v.y; dst[2] = v.z; dst[3] = v.w;
    }
    __syncthreads();

    uint32_t qfrag[8][4];
    {
        const float* qrow = smf + (size_t)(w * 16 + tr) * PADK + tc;
#pragma unroll
        for (int kt = 0; kt < 8; kt++) {
            qfrag[kt][0] = __float_as_uint(qrow[kt * 8]);
            qfrag[kt][1] = __float_as_uint(qrow[8 * PADK + kt * 8]);
            qfrag[kt][2] = __float_as_uint(qrow[kt * 8 + 4]);
            qfrag[kt][3] = __float_as_uint(qrow[8 * PADK + kt * 8 + 4]);
        }
    }
    __syncthreads();

    const uint32_t s0 = smem_u32(smf);

    float oacc[8][4];
#pragma unroll
    for (int nt = 0; nt < 8; nt++)
#pragma unroll
        for (int e = 0; e < 4; e++) oacc[nt][e] = 0.f;

    float m0 = -1e30f, m1 = -1e30f, l0 = 0.f, l1 = 0.f;

    const float CSC = 0.18033688f;   // (1/sqrt(64)) * log2(e)
    const int wrow  = qb + w * 16;
    const int gr0   = wrow + tr;
    const int jmax  = (qb + TQA - 1) / TKA;

#pragma unroll
    for (int rep = 0; rep < 4; rep++) {
        int i = tid + rep * 256;
        int r = i >> 4, c4 = (i & 15) * 4;
        uint32_t soff = (uint32_t)(r * PADK + c4) * 4;
        cp_async16(s0 + soff,             kptr + (size_t)r * D3 + c4);
        cp_async16(s0 + KVT_F * 4 + soff, vptr + (size_t)r * D3 + c4);
    }
    cp_commit();

    for (int j = 0; j <= jmax; j++) {
        const int kb = j * TKA;

        if (j < jmax) {
            const int kb1 = (j + 1) * TKA;
            const uint32_t sst = s0 + (uint32_t)(((j + 1) & 1) * STG_F) * 4;
#pragma unroll
            for (int rep = 0; rep < 4; rep++) {
                int i = tid + rep * 256;
                int r = i >> 4, c4 = (i & 15) * 4;
                uint32_t soff = (uint32_t)(r * PADK + c4) * 4;
                cp_async16(sst + soff,             kptr + (size_t)(kb1 + r) * D3 + c4);
                cp_async16(sst + KVT_F * 4 + soff, vptr + (size_t)(kb1 + r) * D3 + c4);
            }
            cp_commit();
            cp_wait<1>();
        } else {
            cp_wait<0>();
        }
        __syncthreads();

        const float* Ksm = smf + (j & 1) * STG_F;
        const float* Vsm = Ksm + KVT_F;

        if (kb <= wrow + 15) {
            float sacc[8][4];
#pragma unroll
            for (int nt = 0; nt < 8; nt++)
#pragma unroll
                for (int e = 0; e < 4; e++) sacc[nt][e] = 0.f;

#pragma unroll
            for (int kt = 0; kt < 8; kt++) {
#pragma unroll
                for (int nt = 0; nt < 8; nt++) {
                    uint32_t bb[2];
                    const float* krow = Ksm + (size_t)(nt * 8 + tr) * PADK + kt * 8 + tc;
                    bb[0] = __float_as_uint(krow[0]);
                    bb[1] = __float_as_uint(krow[4]);
                    mma_tf32(sacc[nt], qfrag[kt], bb);
                }
            }

            const bool need_mask = (kb + TKA - 1) > wrow;
            float mx0 = -1e30f, mx1 = -1e30f;
#pragma unroll
            for (int nt = 0; nt < 8; nt++) {
                int c0 = kb + nt * 8 + 2 * tc;
                float z0 = sacc[nt][0] * CSC;
                float z1 = sacc[nt][1] * CSC;
                float z2 = sacc[nt][2] * CSC;
                float z3 = sacc[nt][3] * CSC;
                if (need_mask) {
                    if (c0     > gr0) z0 = -1e30f;
                    if (c0 + 1 > gr0) z1 = -1e30f;
                    if (c0     > gr0 + 8) z2 = -1e30f;
                    if (c0 + 1 > gr0 + 8) z3 = -1e30f;
                }
                sacc[nt][0] = z0; sacc[nt][1] = z1;
                sacc[nt][2] = z2; sacc[nt][3] = z3;
                mx0 = fmaxf(mx0, fmaxf(z0, z1));
                mx1 = fmaxf(mx1, fmaxf(z2, z3));
            }
            mx0 = fmaxf(mx0, __shfl_xor_sync(0xffffffffu, mx0, 1));
            mx0 = fmaxf(mx0, __shfl_xor_sync(0xffffffffu, mx0, 2));
            mx1 = fmaxf(mx1, __shfl_xor_sync(0xffffffffu, mx1, 1));
            mx1 = fmaxf(mx1, __shfl_xor_sync(0xffffffffu, mx1, 2));

            float m0n = fmaxf(m0, mx0);
            float m1n = fmaxf(m1, mx1);
            float f0 = exp2f(m0 - m0n);
            float f1 = exp2f(m1 - m1n);

            uint32_t pcu[8][4];
            float sum0 = 0.f, sum1 = 0.f;
#pragma unroll
            for (int nt = 0; nt < 8; nt++) {
                float p00 = exp2f(sacc[nt][0] - m0n);
                float p01 = exp2f(sacc[nt][1] - m0n);
                float p10 = exp2f(sacc[nt][2] - m1n);
                float p11 = exp2f(sacc[nt][3] - m1n);
                sum0 += p00 + p01;
                sum1 += p10 + p11;
                pcu[nt][0] = f2tf32(p00);
                pcu[nt][1] = f2tf32(p01);
                pcu[nt][2] = f2tf32(p10);
                pcu[nt][3] = f2tf32(p11);
            }
            sum0 += __shfl_xor_sync(0xffffffffu, sum0, 1);
            sum0 += __shfl_xor_sync(0xffffffffu, sum0, 2);
            sum1 += __shfl_xor_sync(0xffffffffu, sum1, 1);
            sum1 += __shfl_xor_sync(0xffffffffu, sum1, 2);

            l0 = l0 * f0 + sum0;
            l1 = l1 * f1 + sum1;
            m0 = m0n; m1 = m1n;
#pragma unroll
            for (int nt = 0; nt < 8; nt++) {
                oacc[nt][0] *= f0; oacc[nt][1] *= f0;
                oacc[nt][2] *= f1; oacc[nt][3] *= f1;
            }

            const int basel = lane & ~3;
            const int sl  = basel + (tc >> 1);
            const int sl2 = sl + 2;
            const bool odd = (tc & 1);
#pragma unroll
            for (int kt = 0; kt < 8; kt++) {
                uint32_t x0 = __shfl_sync(0xffffffffu, pcu[kt][0], sl);
                uint32_t x1 = __shfl_sync(0xffffffffu, pcu[kt][1], sl);
                uint32_t y0 = __shfl_sync(0xffffffffu, pcu[kt][0], sl2);
                uint32_t y1 = __shfl_sync(0xffffffffu, pcu[kt][1], sl2);
                uint32_t z0 = __shfl_sync(0xffffffffu, pcu[kt][2], sl);
                uint32_t z1 = __shfl_sync(0xffffffffu, pcu[kt][3], sl);
                uint32_t w0 = __shfl_sync(0xffffffffu, pcu[kt][2], sl2);
                uint32_t w1 = __shfl_sync(0xffffffffu, pcu[kt][3], sl2);
                uint32_t pa[4];
                pa[0] = odd ? x1 : x0;
                pa[1] = odd ? z1 : z0;
                pa[2] = odd ? y1 : y0;
                pa[3] = odd ? w1 : w0;
#pragma unroll
                for (int nt = 0; nt < 8; nt++) {
                    uint32_t vb[2];
                    const float* vrow = Vsm + (size_t)(kt * 8 + tc) * PADK + nt * 8 + tr;
                    vb[0] = __float_as_uint(vrow[0]);
                    vb[1] = __float_as_uint(vrow[4 * PADK]);
                    mma_tf32(oacc[nt], pa, vb);
                }
            }
        }
        __syncthreads();
    }

    // Epilogue: normalize, round to tf32, write to g_attn
    float il0 = 1.0f / l0;
    float il1 = 1.0f / l1;
    float* obase = g_attn + (size_t)(rowbase + gr0) * EMBED + h * HDIM + 2 * tc;
#pragma unroll
    for (int nt = 0; nt < 8; nt++) {
        *reinterpret_cast<float2*>(obase + nt * 8) =
            make_float2(roundtf(oacc[nt][0] * il0), roundtf(oacc[nt][1] * il0));
        *reinterpret_cast<float2*>(obase + 8 * EMBED + nt * 8) =
            make_float2(roundtf(oacc[nt][2] * il1), roundtf(oacc[nt][3] * il1));
    }
}

// ---------------------------------------------------------------------------
// Launch
// ---------------------------------------------------------------------------
extern "C" void kernel_launch(void* const* d_in, const int* in_sizes, int n_in,
                              void* d_out, int out_size)
{
    const float* x     = (const float*)d_in[0];
    const float* qkv_w = (const float*)d_in[1];
    const float* out_w = (const float*)d_in[2];
    float* out = (float*)d_out;

    static bool attr_done = false;
    if (!attr_done) {
        cudaFuncSetAttribute(gemm_tf32<true>,  cudaFuncAttributeMaxDynamicSharedMemorySize, GEMM_SMEM);
        cudaFuncSetAttribute(gemm_tf32<false>, cudaFuncAttributeMaxDynamicSharedMemorySize, GEMM_SMEM);
        cudaFuncSetAttribute(attn_tc_kernel,   cudaFuncAttributeMaxDynamicSharedMemorySize, ATT_SMEM);
        attr_done = true;
    }

    float *qkv, *attn, *xt, *w1t, *w2t;
    cudaGetSymbolAddress((void**)&qkv,  g_qkv);
    cudaGetSymbolAddress((void**)&attn, g_attn);
    cudaGetSymbolAddress((void**)&xt,   g_x_t);
    cudaGetSymbolAddress((void**)&w1t,  g_w1_t);
    cudaGetSymbolAddress((void**)&w2t,  g_w2_t);

    // 0) pre-round inputs to tf32
    {
        int n1 = MROWS * EMBED / 4;
        round_tf32_kernel<<<(n1 + 255) / 256, 256>>>(x, xt, n1);
        int n2 = D3 * EMBED / 4;
        round_tf32_kernel<<<(n2 + 255) / 256, 256>>>(qkv_w, w1t, n2);
        int n3 = EMBED * EMBED / 4;
        round_tf32_kernel<<<(n3 + 255) / 256, 256>>>(out_w, w2t, n3);
    }

    // 1) QKV projection (tf32, output rounded for attention)
    {
        dim3 grid(D3 / 128, MROWS / 128);
        gemm_tf32<true><<<grid, 128, GEMM_SMEM>>>(xt, w1t, qkv, MROWS, D3, EMBED);
    }

    // 2) Causal flash attention (tf32, CVT-free fragments, rounded output)
    {
        dim3 grid(SEQ / TQA, NHEADS, BATCH);
        attn_tc_kernel<<<grid, 256, ATT_SMEM>>>();
    }

    // 3) Output projection (tf32, full-precision fp32 output)
    {
        dim3 grid(EMBED / 128, MROWS / 128);
        gemm_tf32<false><<<grid, 128, GEMM_SMEM>>>(attn, w2t, out, MROWS, EMBED, EMBED);
    }
}